// round 12
// baseline (speedup 1.0000x reference)
#include <cuda_runtime.h>
#include <cuda_fp16.h>
#include <math.h>
#include <stdint.h>

#define B  32768
#define D  512
#define H  256
#define OO 128
#define E_ 10
#define T_ 3
#define G_ 64
#define NS 4
#define NT_TASK 2
#define NE (NS + NT_TASK)

typedef __half h16;

// ---------------- scratch (allocation-free) ----------------
__device__ h16   g_xh[(size_t)B * D];
__device__ h16   g_w1t[(size_t)E_ * H * D];    // [E][N=256][K=512] fp16
__device__ h16   g_w2t[(size_t)E_ * H * H];    // [E][256][256]
__device__ h16   g_w3t[(size_t)E_ * OO * H];   // [E][128][256]
__device__ h16   g_wgt[(size_t)256 * D];       // combined gate W1^T [256][512]
__device__ h16   g_eo[(size_t)E_ * B * OO];    // expert outputs, fp16
__device__ float g_gw[(size_t)T_ * B * NE];
__device__ float g_sgw[(size_t)B * E_];

// ---------------- helpers ----------------
__device__ __forceinline__ void mma_fp16(float* c, const unsigned* a, const unsigned* b) {
    asm volatile(
        "mma.sync.aligned.m16n8k16.row.col.f32.f16.f16.f32 "
        "{%0,%1,%2,%3}, {%4,%5,%6,%7}, {%8,%9}, {%0,%1,%2,%3};\n"
        : "+f"(c[0]), "+f"(c[1]), "+f"(c[2]), "+f"(c[3])
        : "r"(a[0]), "r"(a[1]), "r"(a[2]), "r"(a[3]), "r"(b[0]), "r"(b[1]));
}
__device__ __forceinline__ unsigned pack_h2(h16 a, h16 b) {
    return (unsigned)__half_as_ushort(a) | ((unsigned)__half_as_ushort(b) << 16);
}
__device__ __forceinline__ void cp16(void* s, const void* g) {
    unsigned sa = (unsigned)__cvta_generic_to_shared(s);
    asm volatile("cp.async.cg.shared.global [%0], [%1], 16;\n" :: "r"(sa), "l"(g));
}
__device__ __forceinline__ void cp_commit() { asm volatile("cp.async.commit_group;\n"); }
template <int N2> __device__ __forceinline__ void cp_wait() {
    asm volatile("cp.async.wait_group %0;\n" :: "n"(N2));
}
__device__ __forceinline__ unsigned lds_u32(const void* p) {
    return (unsigned)__cvta_generic_to_shared(p);
}
__device__ __forceinline__ void ldsm_x4(unsigned* r, unsigned addr) {
    asm volatile("ldmatrix.sync.aligned.m8n8.x4.shared.b16 {%0,%1,%2,%3}, [%4];"
        : "=r"(r[0]), "=r"(r[1]), "=r"(r[2]), "=r"(r[3]) : "r"(addr));
}

// ---------------- prep kernels (merged) ----------------
__global__ void prep_x_gate(const float4* __restrict__ x4, unsigned* __restrict__ xh2,
                            const float* __restrict__ tg_w1, const float* __restrict__ sg_w1,
                            h16* __restrict__ wgt)
{
    const int bx = blockIdx.x, tid = threadIdx.x;
    if (bx < 16384) {
        int i = bx * 256 + tid;
        float4 v = x4[i];
        xh2[i * 2]     = pack_h2(__float2half_rn(v.x), __float2half_rn(v.y));
        xh2[i * 2 + 1] = pack_h2(__float2half_rn(v.z), __float2half_rn(v.w));
    } else {
        int i = (bx - 16384) * 256 + tid;
        int n = i >> 9, d = i & 511;
        float v;
        if (n < 192) {
            int t = n >> 6, g = n & 63;
            v = tg_w1[((size_t)t * D + d) * G_ + g];
        } else {
            v = sg_w1[(size_t)d * G_ + (n - 192)];
        }
        wgt[(size_t)n * D + d] = __float2half_rn(v);
    }
}

__global__ void prep_weights(const float* __restrict__ ew1, const float* __restrict__ ew2,
                             const float* __restrict__ ew3,
                             h16* __restrict__ w1t, h16* __restrict__ w2t, h16* __restrict__ w3t)
{
    __shared__ float t[32][33];
    const int e = blockIdx.y, bx = blockIdx.x, tid = threadIdx.x;
    const float* W; h16* T; int K, N, k0, n0;
    if (bx < 128)      { W = ew1; T = w1t; K = D; N = H;  k0 = (bx & 15) * 32;        n0 = (bx >> 4) * 32; }
    else if (bx < 192) { W = ew2; T = w2t; K = H; N = H;  k0 = ((bx - 128) & 7) * 32; n0 = ((bx - 128) >> 3) * 32; }
    else               { W = ew3; T = w3t; K = H; N = OO; k0 = ((bx - 192) & 7) * 32; n0 = ((bx - 192) >> 3) * 32; }
    const float* We = W + (size_t)e * K * N;
    for (int i = tid; i < 1024; i += 256) {
        int r = i >> 5, c = i & 31;
        t[r][c] = We[(size_t)(k0 + r) * N + n0 + c];
    }
    __syncthreads();
    size_t base = (size_t)e * N * K;
    for (int i = tid; i < 1024; i += 256) {
        int nn = i >> 5, kk = i & 31;
        T[base + (size_t)(n0 + nn) * K + k0 + kk] = __float2half_rn(t[kk][nn]);
    }
}

// ---------------------------------------------------------------------------
// Fused expert tower. CTA tile 128x256, 512 threads, 16 warps (4m x 4n),
// warp tile 32x64. One CTA per SM.
// ---------------------------------------------------------------------------
#define TOW_THREADS 512

struct SmemT {
    h16   sB[2][256][40];   // 40 KB
    h16   sX[2][128][40];   // 20 KB
    h16   sH[128][264];     // 66 KB
    float red[4][128][2];   //  4 KB
};

__global__ void __launch_bounds__(TOW_THREADS, 1)
expert_fused(const h16* __restrict__ xh,
             const h16* __restrict__ w1t, const h16* __restrict__ w2t, const h16* __restrict__ w3t,
             const float* __restrict__ eb1, const float* __restrict__ eg1, const float* __restrict__ ebt1,
             const float* __restrict__ eb2, const float* __restrict__ eg2, const float* __restrict__ ebt2,
             const float* __restrict__ eb3, const float* __restrict__ eg3, const float* __restrict__ ebt3,
             h16* __restrict__ eo)
{
    extern __shared__ char raw[];
    SmemT& sm = *reinterpret_cast<SmemT*>(raw);

    const int e   = blockIdx.x;
    const int b0  = blockIdx.y * 128;
    const int tid = threadIdx.x;
    const int wid = tid >> 5, lane = tid & 31;
    const int warp_m = wid & 3, warp_n = wid >> 2;   // 4 x 4
    const int gr = lane >> 2, tg = lane & 3;
    const int l8 = lane & 7, lm = lane >> 3;
    const int a_row0 = warp_m * 32 + (lm & 1) * 8 + l8;  // + mt*16
    const int a_kx   = (lm >> 1) * 8;
    const int b_row8 = (lm >> 1) * 8 + l8;               // + colbase + np*16
    const int b_kx   = (lm & 1) * 8;

    const h16* W1 = w1t + (size_t)e * H * D;
    const h16* W2 = w2t + (size_t)e * H * H;
    const h16* W3 = w3t + (size_t)e * OO * H;

    auto loadB = [&](const h16* T, int rows, int K, int buf, int k0) {
        for (int i = tid; i < rows * 4; i += TOW_THREADS) {
            int n = i >> 2, c = i & 3;
            cp16(&sm.sB[buf][n][c * 8], T + (size_t)n * K + k0 + c * 8);
        }
    };
    auto loadX = [&](int buf, int k0) {
        int r = tid >> 2, c = tid & 3;   // 128 rows x 4 chunks = 512 threads
        cp16(&sm.sX[buf][r][c * 8], xh + (size_t)(b0 + r) * D + k0 + c * 8);
    };

    float acc[2][8][4];
    float s[2][2], q[2][2], mean[2][2], rstd[2][2];

    // =================== Layer 1: 128x512 @ W1 -> 128x256 ===================
#pragma unroll
    for (int mt = 0; mt < 2; mt++)
#pragma unroll
        for (int nt = 0; nt < 8; nt++)
#pragma unroll
            for (int j = 0; j < 4; j++) acc[mt][nt][j] = 0.f;

    int buf = 0;
    loadX(0, 0);
    loadB(W1, 256, D, 0, 0);
    cp_commit();

    for (int ks = 0; ks < 16; ks++) {
        if (ks < 15) { loadX(buf ^ 1, (ks + 1) * 32); loadB(W1, 256, D, buf ^ 1, (ks + 1) * 32); }
        cp_commit();
        cp_wait<1>(); __syncthreads();
#pragma unroll
        for (int ksub = 0; ksub < 2; ksub++) {
            const int koff = ksub * 16;
            unsigned a0[4], a1[4], bb[4][4];
            ldsm_x4(a0, lds_u32(&sm.sX[buf][a_row0][koff + a_kx]));
            ldsm_x4(a1, lds_u32(&sm.sX[buf][a_row0 + 16][koff + a_kx]));
#pragma unroll
            for (int np = 0; np < 4; np++)
                ldsm_x4(bb[np], lds_u32(&sm.sB[buf][warp_n * 64 + np * 16 + b_row8][koff + b_kx]));
#pragma unroll
            for (int np = 0; np < 4; np++) {
                mma_fp16(acc[0][2 * np],     a0, bb[np]);
                mma_fp16(acc[0][2 * np + 1], a0, bb[np] + 2);
                mma_fp16(acc[1][2 * np],     a1, bb[np]);
                mma_fp16(acc[1][2 * np + 1], a1, bb[np] + 2);
            }
        }
        __syncthreads();
        buf ^= 1;
    }
    loadB(W2, 256, H, 0, 0);
    cp_commit();

    // ---- epilogue 1 -> sH ----
    {
        const float* be  = eb1  + (size_t)e * H;
        const float* ge  = eg1  + (size_t)e * H;
        const float* bte = ebt1 + (size_t)e * H;
        const int cbase = warp_n * 64 + tg * 2;
#pragma unroll
        for (int mt = 0; mt < 2; mt++) { s[mt][0] = s[mt][1] = q[mt][0] = q[mt][1] = 0.f; }
#pragma unroll
        for (int mt = 0; mt < 2; mt++)
#pragma unroll
            for (int nt = 0; nt < 8; nt++) {
                int c = cbase + nt * 8;
                float bv0 = be[c], bv1 = be[c + 1];
                acc[mt][nt][0] += bv0; acc[mt][nt][1] += bv1;
                acc[mt][nt][2] += bv0; acc[mt][nt][3] += bv1;
                s[mt][0] += acc[mt][nt][0] + acc[mt][nt][1];
                q[mt][0] = fmaf(acc[mt][nt][0], acc[mt][nt][0], fmaf(acc[mt][nt][1], acc[mt][nt][1], q[mt][0]));
                s[mt][1] += acc[mt][nt][2] + acc[mt][nt][3];
                q[mt][1] = fmaf(acc[mt][nt][2], acc[mt][nt][2], fmaf(acc[mt][nt][3], acc[mt][nt][3], q[mt][1]));
            }
#pragma unroll
        for (int mt = 0; mt < 2; mt++)
#pragma unroll
            for (int h = 0; h < 2; h++)
#pragma unroll
                for (int off = 1; off <= 2; off <<= 1) {
                    s[mt][h] += __shfl_xor_sync(0xffffffffu, s[mt][h], off);
                    q[mt][h] += __shfl_xor_sync(0xffffffffu, q[mt][h], off);
                }
        __syncthreads();
        if (tg == 0) {
#pragma unroll
            for (int mt = 0; mt < 2; mt++)
#pragma unroll
                for (int h = 0; h < 2; h++) {
                    int r = warp_m * 32 + mt * 16 + gr + h * 8;
                    sm.red[warp_n][r][0] = s[mt][h];
                    sm.red[warp_n][r][1] = q[mt][h];
                }
        }
        __syncthreads();
        const float invN = 1.0f / H;
#pragma unroll
        for (int mt = 0; mt < 2; mt++)
#pragma unroll
            for (int h = 0; h < 2; h++) {
                int r = warp_m * 32 + mt * 16 + gr + h * 8;
                float ss = sm.red[0][r][0] + sm.red[1][r][0] + sm.red[2][r][0] + sm.red[3][r][0];
                float qq = sm.red[0][r][1] + sm.red[1][r][1] + sm.red[2][r][1] + sm.red[3][r][1];
                float m = ss * invN;
                mean[mt][h] = m;
                rstd[mt][h] = rsqrtf(qq * invN - m * m + 1e-5f);
            }
#pragma unroll
        for (int mt = 0; mt < 2; mt++) {
            int r0 = warp_m * 32 + mt * 16 + gr;
#pragma unroll
            for (int nt = 0; nt < 8; nt++) {
                int c = cbase + nt * 8;
                float g0 = ge[c], g1 = ge[c + 1], t0 = bte[c], t1 = bte[c + 1];
                float v00 = fmaxf((acc[mt][nt][0] - mean[mt][0]) * rstd[mt][0] * g0 + t0, 0.f);
                float v01 = fmaxf((acc[mt][nt][1] - mean[mt][0]) * rstd[mt][0] * g1 + t1, 0.f);
                float v10 = fmaxf((acc[mt][nt][2] - mean[mt][1]) * rstd[mt][1] * g0 + t0, 0.f);
                float v11 = fmaxf((acc[mt][nt][3] - mean[mt][1]) * rstd[mt][1] * g1 + t1, 0.f);
                *(unsigned*)&sm.sH[r0][c]     = pack_h2(__float2half_rn(v00), __float2half_rn(v01));
                *(unsigned*)&sm.sH[r0 + 8][c] = pack_h2(__float2half_rn(v10), __float2half_rn(v11));
            }
        }
    }

    // =================== Layer 2: sH @ W2 -> 128x256 ===================
#pragma unroll
    for (int mt = 0; mt < 2; mt++)
#pragma unroll
        for (int nt = 0; nt < 8; nt++)
#pragma unroll
            for (int j = 0; j < 4; j++) acc[mt][nt][j] = 0.f;

    buf = 0;
    for (int ks = 0; ks < 8; ks++) {
        if (ks < 7) loadB(W2, 256, H, buf ^ 1, (ks + 1) * 32);
        cp_commit();
        cp_wait<1>(); __syncthreads();
#pragma unroll
        for (int ksub = 0; ksub < 2; ksub++) {
            const int koffA = ks * 32 + ksub * 16;
            const int koffB = ksub * 16;
            unsigned a0[4], a1[4], bb[4][4];
            ldsm_x4(a0, lds_u32(&sm.sH[a_row0][koffA + a_kx]));
            ldsm_x4(a1, lds_u32(&sm.sH[a_row0 + 16][koffA + a_kx]));
#pragma unroll
            for (int np = 0; np < 4; np++)
                ldsm_x4(bb[np], lds_u32(&sm.sB[buf][warp_n * 64 + np * 16 + b_row8][koffB + b_kx]));
#pragma unroll
            for (int np = 0; np < 4; np++) {
                mma_fp16(acc[0][2 * np],     a0, bb[np]);
                mma_fp16(acc[0][2 * np + 1], a0, bb[np] + 2);
                mma_fp16(acc[1][2 * np],     a1, bb[np]);
                mma_fp16(acc[1][2 * np + 1], a1, bb[np] + 2);
            }
        }
        __syncthreads();
        buf ^= 1;
    }
    loadB(W3, 128, H, 0, 0);
    cp_commit();

    // ---- epilogue 2 -> sH ----
    {
        const float* be  = eb2  + (size_t)e * H;
        const float* ge  = eg2  + (size_t)e * H;
        const float* bte = ebt2 + (size_t)e * H;
        const int cbase = warp_n * 64 + tg * 2;
#pragma unroll
        for (int mt = 0; mt < 2; mt++) { s[mt][0] = s[mt][1] = q[mt][0] = q[mt][1] = 0.f; }
#pragma unroll
        for (int mt = 0; mt < 2; mt++)
#pragma unroll
            for (int nt = 0; nt < 8; nt++) {
                int c = cbase + nt * 8;
                float bv0 = be[c], bv1 = be[c + 1];
                acc[mt][nt][0] += bv0; acc[mt][nt][1] += bv1;
                acc[mt][nt][2] += bv0; acc[mt][nt][3] += bv1;
                s[mt][0] += acc[mt][nt][0] + acc[mt][nt][1];
                q[mt][0] = fmaf(acc[mt][nt][0], acc[mt][nt][0], fmaf(acc[mt][nt][1], acc[mt][nt][1], q[mt][0]));
                s[mt][1] += acc[mt][nt][2] + acc[mt][nt][3];
                q[mt][1] = fmaf(acc[mt][nt][2], acc[mt][nt][2], fmaf(acc[mt][nt][3], acc[mt][nt][3], q[mt][1]));
            }
#pragma unroll
        for (int mt = 0; mt < 2; mt++)
#pragma unroll
            for (int h = 0; h < 2; h++)
#pragma unroll
                for (int off = 1; off <= 2; off <<= 1) {
                    s[mt][h] += __shfl_xor_sync(0xffffffffu, s[mt][h], off);
                    q[mt][h] += __shfl_xor_sync(0xffffffffu, q[mt][h], off);
                }
        __syncthreads();
        if (tg == 0) {
#pragma unroll
            for (int mt = 0; mt < 2; mt++)
#pragma unroll
                for (int h = 0; h < 2; h++) {
                    int r = warp_m * 32 + mt * 16 + gr + h * 8;
                    sm.red[warp_n][r][0] = s[mt][h];
                    sm.red[warp_n][r][1] = q[mt][h];
                }
        }
        __syncthreads();
        const float invN = 1.0f / H;
#pragma unroll
        for (int mt = 0; mt < 2; mt++)
#pragma unroll
            for (int h = 0; h < 2; h++) {
                int r = warp_m * 32 + mt * 16 + gr + h * 8;
                float ss = sm.red[0][r][0] + sm.red[1][r][0] + sm.red[2][r][0] + sm.red[3][r][0];
                float qq = sm.red[0][r][1] + sm.red[1][r][1] + sm.red[2][r][1] + sm.red[3][r][1];
                float m = ss * invN;
                mean[mt][h] = m;
                rstd[mt][h] = rsqrtf(qq * invN - m * m + 1e-5f);
            }
        __syncthreads();   // all reads of sH (L2 mainloop) done before overwrite
#pragma unroll
        for (int mt = 0; mt < 2; mt++) {
            int r0 = warp_m * 32 + mt * 16 + gr;
#pragma unroll
            for (int nt = 0; nt < 8; nt++) {
                int c = cbase + nt * 8;
                float g0 = ge[c], g1 = ge[c + 1], t0 = bte[c], t1 = bte[c + 1];
                float v00 = fmaxf((acc[mt][nt][0] - mean[mt][0]) * rstd[mt][0] * g0 + t0, 0.f);
                float v01 = fmaxf((acc[mt][nt][1] - mean[mt][0]) * rstd[mt][0] * g1 + t1, 0.f);
                float v10 = fmaxf((acc[mt][nt][2] - mean[mt][1]) * rstd[mt][1] * g0 + t0, 0.f);
                float v11 = fmaxf((acc[mt][nt][3] - mean[mt][1]) * rstd[mt][1] * g1 + t1, 0.f);
                *(unsigned*)&sm.sH[r0][c]     = pack_h2(__float2half_rn(v00), __float2half_rn(v01));
                *(unsigned*)&sm.sH[r0 + 8][c] = pack_h2(__float2half_rn(v10), __float2half_rn(v11));
            }
        }
    }
    __syncthreads();

    // =================== Layer 3: sH @ W3 -> 128x128 ===================
#pragma unroll
    for (int mt = 0; mt < 2; mt++)
#pragma unroll
        for (int nt = 0; nt < 4; nt++)
#pragma unroll
            for (int j = 0; j < 4; j++) acc[mt][nt][j] = 0.f;

    buf = 0;
    for (int ks = 0; ks < 8; ks++) {
        if (ks < 7) loadB(W3, 128, H, buf ^ 1, (ks + 1) * 32);
        cp_commit();
        cp_wait<1>(); __syncthreads();
#pragma unroll
        for (int ksub = 0; ksub < 2; ksub++) {
            const int koffA = ks * 32 + ksub * 16;
            const int koffB = ksub * 16;
            unsigned a0[4], a1[4], bb[2][4];
            ldsm_x4(a0, lds_u32(&sm.sH[a_row0][koffA + a_kx]));
            ldsm_x4(a1, lds_u32(&sm.sH[a_row0 + 16][koffA + a_kx]));
#pragma unroll
            for (int np = 0; np < 2; np++)
                ldsm_x4(bb[np], lds_u32(&sm.sB[buf][warp_n * 32 + np * 16 + b_row8][koffB + b_kx]));
#pragma unroll
            for (int np = 0; np < 2; np++) {
                mma_fp16(acc[0][2 * np],     a0, bb[np]);
                mma_fp16(acc[0][2 * np + 1], a0, bb[np] + 2);
                mma_fp16(acc[1][2 * np],     a1, bb[np]);
                mma_fp16(acc[1][2 * np + 1], a1, bb[np] + 2);
            }
        }
        __syncthreads();
        buf ^= 1;
    }

    // ---- epilogue 3 -> eo (fp16) ----
    {
        const float* be  = eb3  + (size_t)e * OO;
        const float* ge  = eg3  + (size_t)e * OO;
        const float* bte = ebt3 + (size_t)e * OO;
        const int cbase = warp_n * 32 + tg * 2;
#pragma unroll
        for (int mt = 0; mt < 2; mt++) { s[mt][0] = s[mt][1] = q[mt][0] = q[mt][1] = 0.f; }
#pragma unroll
        for (int mt = 0; mt < 2; mt++)
#pragma unroll
            for (int nt = 0; nt < 4; nt++) {
                int c = cbase + nt * 8;
                float bv0 = be[c], bv1 = be[c + 1];
                acc[mt][nt][0] += bv0; acc[mt][nt][1] += bv1;
                acc[mt][nt][2] += bv0; acc[mt][nt][3] += bv1;
                s[mt][0] += acc[mt][nt][0] + acc[mt][nt][1];
                q[mt][0] = fmaf(acc[mt][nt][0], acc[mt][nt][0], fmaf(acc[mt][nt][1], acc[mt][nt][1], q[mt][0]));
                s[mt][1] += acc[mt][nt][2] + acc[mt][nt][3];
                q[mt][1] = fmaf(acc[mt][nt][2], acc[mt][nt][2], fmaf(acc[mt][nt][3], acc[mt][nt][3], q[mt][1]));
            }
#pragma unroll
        for (int mt = 0; mt < 2; mt++)
#pragma unroll
            for (int h = 0; h < 2; h++)
#pragma unroll
                for (int off = 1; off <= 2; off <<= 1) {
                    s[mt][h] += __shfl_xor_sync(0xffffffffu, s[mt][h], off);
                    q[mt][h] += __shfl_xor_sync(0xffffffffu, q[mt][h], off);
                }
        __syncthreads();
        if (tg == 0) {
#pragma unroll
            for (int mt = 0; mt < 2; mt++)
#pragma unroll
                for (int h = 0; h < 2; h++) {
                    int r = warp_m * 32 + mt * 16 + gr + h * 8;
                    sm.red[warp_n][r][0] = s[mt][h];
                    sm.red[warp_n][r][1] = q[mt][h];
                }
        }
        __syncthreads();
        const float invN = 1.0f / OO;
#pragma unroll
        for (int mt = 0; mt < 2; mt++)
#pragma unroll
            for (int h = 0; h < 2; h++) {
                int r = warp_m * 32 + mt * 16 + gr + h * 8;
                float ss = sm.red[0][r][0] + sm.red[1][r][0] + sm.red[2][r][0] + sm.red[3][r][0];
                float qq = sm.red[0][r][1] + sm.red[1][r][1] + sm.red[2][r][1] + sm.red[3][r][1];
                float m = ss * invN;
                mean[mt][h] = m;
                rstd[mt][h] = rsqrtf(qq * invN - m * m + 1e-5f);
            }
#pragma unroll
        for (int mt = 0; mt < 2; mt++) {
            int r0 = warp_m * 32 + mt * 16 + gr;
            size_t row0 = ((size_t)e * B + b0 + r0) * OO;
            size_t row1 = row0 + (size_t)8 * OO;
#pragma unroll
            for (int nt = 0; nt < 4; nt++) {
                int c = cbase + nt * 8;
                float g0 = ge[c], g1 = ge[c + 1], t0 = bte[c], t1 = bte[c + 1];
                float v00 = fmaxf((acc[mt][nt][0] - mean[mt][0]) * rstd[mt][0] * g0 + t0, 0.f);
                float v01 = fmaxf((acc[mt][nt][1] - mean[mt][0]) * rstd[mt][0] * g1 + t1, 0.f);
                float v10 = fmaxf((acc[mt][nt][2] - mean[mt][1]) * rstd[mt][1] * g0 + t0, 0.f);
                float v11 = fmaxf((acc[mt][nt][3] - mean[mt][1]) * rstd[mt][1] * g1 + t1, 0.f);
                *(unsigned*)&eo[row0 + c] = pack_h2(__float2half_rn(v00), __float2half_rn(v01));
                *(unsigned*)&eo[row1 + c] = pack_h2(__float2half_rn(v10), __float2half_rn(v11));
            }
        }
    }
}

// ---------------------------------------------------------------------------
// Fused gates (unchanged — passing, small share of runtime).
// ---------------------------------------------------------------------------
struct GSmem {
    h16   sB[2][256][40];
    h16   sX[2][64][40];
    h16   ghs[64][266];
    float w2s[T_ * G_ * NE];
    float sw2s[G_ * E_];
    float b1s[256];
    float b2s[T_ * NE + E_];
};

__global__ void __launch_bounds__(256, 2)
gate_fused(const h16* __restrict__ xh, const h16* __restrict__ wgt,
           const float* __restrict__ tg_b1, const float* __restrict__ sg_b1,
           const float* __restrict__ tg_w2, const float* __restrict__ tg_b2,
           const float* __restrict__ sg_w2, const float* __restrict__ sg_b2,
           float* __restrict__ gw, float* __restrict__ sgw)
{
    extern __shared__ char raw[];
    GSmem& sm = *reinterpret_cast<GSmem*>(raw);

    const int b0  = blockIdx.x * 64;
    const int tid = threadIdx.x;
    const int wid = tid >> 5, lane = tid & 31;
    const int warp_m = wid & 3, warp_n = wid >> 2;
    const int gr = lane >> 2, tg = lane & 3;
    const int ar = warp_m * 16 + gr;
    const int l8 = lane & 7, lm = lane >> 3;
    const int a_row = warp_m * 16 + (lm & 1) * 8 + l8;
    const int a_kx  = (lm >> 1) * 8;
    const int b_row8 = (lm >> 1) * 8 + l8;
    const int b_kx   = (lm & 1) * 8;

    for (int i = tid; i < T_ * G_ * NE; i += 256) sm.w2s[i] = tg_w2[i];
    for (int i = tid; i < G_ * E_; i += 256) sm.sw2s[i] = sg_w2[i];
    sm.b1s[tid] = (tid < 192) ? tg_b1[tid] : sg_b1[tid - 192];
    if (tid < T_ * NE) sm.b2s[tid] = tg_b2[tid];
    else if (tid < T_ * NE + E_) sm.b2s[tid] = sg_b2[tid - T_ * NE];

    auto loadB = [&](int buf, int k0) {
        for (int i = tid; i < 256 * 4; i += 256) {
            int n = i >> 2, c = i & 3;
            cp16(&sm.sB[buf][n][c * 8], wgt + (size_t)n * D + k0 + c * 8);
        }
    };
    auto loadX = [&](int buf, int k0) {
        int r = tid >> 2, c = tid & 3;
        cp16(&sm.sX[buf][r][c * 8], xh + (size_t)(b0 + r) * D + k0 + c * 8);
    };

    float acc[16][4];
#pragma unroll
    for (int nt = 0; nt < 16; nt++)
#pragma unroll
        for (int j = 0; j < 4; j++) acc[nt][j] = 0.f;

    int buf = 0;
    loadX(0, 0);
    loadB(0, 0);
    cp_commit();

    for (int ks = 0; ks < 16; ks++) {
        if (ks < 15) { loadX(buf ^ 1, (ks + 1) * 32); loadB(buf ^ 1, (ks + 1) * 32); }
        cp_commit();
        cp_wait<1>(); __syncthreads();
#pragma unroll
        for (int ksub = 0; ksub < 2; ksub++) {
            const int koff = ksub * 16;
            unsigned ah[4];
            ldsm_x4(ah, lds_u32(&sm.sX[buf][a_row][koff + a_kx]));
#pragma unroll
            for (int np = 0; np < 8; np++) {
                unsigned bb[4];
                ldsm_x4(bb, lds_u32(&sm.sB[buf][warp_n * 128 + np * 16 + b_row8][koff + b_kx]));
                mma_fp16(acc[2 * np],     ah, bb);
                mma_fp16(acc[2 * np + 1], ah, bb + 2);
            }
        }
        __syncthreads();
        buf ^= 1;
    }

    {
        const int cbase = warp_n * 128 + tg * 2;
#pragma unroll
        for (int nt = 0; nt < 16; nt++) {
            int c = cbase + nt * 8;
            float bv0 = sm.b1s[c], bv1 = sm.b1s[c + 1];
            float v00 = fmaxf(acc[nt][0] + bv0, 0.f);
            float v01 = fmaxf(acc[nt][1] + bv1, 0.f);
            float v10 = fmaxf(acc[nt][2] + bv0, 0.f);
            float v11 = fmaxf(acc[nt][3] + bv1, 0.f);
            *(unsigned*)&sm.ghs[ar][c]     = pack_h2(__float2half_rn(v00), __float2half_rn(v01));
            *(unsigned*)&sm.ghs[ar + 8][c] = pack_h2(__float2half_rn(v10), __float2half_rn(v11));
        }
    }
    __syncthreads();

    if (tid < 192) {
        const int row = tid & 63, t = tid >> 6;
        float lg[NE];
#pragma unroll
        for (int j = 0; j < NE; j++) lg[j] = sm.b2s[t * NE + j];
        for (int g = 0; g < G_; g++) {
            float gv = __half2float(sm.ghs[row][t * 64 + g]);
            const float* w = &sm.w2s[(t * G_ + g) * NE];
#pragma unroll
            for (int j = 0; j < NE; j++) lg[j] = fmaf(gv, w[j], lg[j]);
        }
        float mx = -1e30f;
#pragma unroll
        for (int j = 0; j < NE; j++) mx = fmaxf(mx, lg[j]);
        float sum = 0.f;
#pragma unroll
        for (int j = 0; j < NE; j++) { lg[j] = __expf(lg[j] - mx); sum += lg[j]; }
        float inv = 1.0f / sum;
#pragma unroll
        for (int j = 0; j < NE; j++)
            gw[((size_t)t * B + b0 + row) * NE + j] = lg[j] * inv;
    } else {
        const int row = tid - 192;
        float lg[E_];
#pragma unroll
        for (int j = 0; j < E_; j++) lg[j] = sm.b2s[T_ * NE + j];
        for (int g = 0; g < G_; g++) {
            float gv = __half2float(sm.ghs[row][192 + g]);
            const float* w = &sm.sw2s[g * E_];
#pragma unroll
            for (int j = 0; j < E_; j++) lg[j] = fmaf(gv, w[j], lg[j]);
        }
        float mx = -1e30f;
#pragma unroll
        for (int j = 0; j < E_; j++) mx = fmaxf(mx, lg[j]);
        float sum = 0.f;
#pragma unroll
        for (int j = 0; j < E_; j++) { lg[j] = __expf(lg[j] - mx); sum += lg[j]; }
        float inv = 1.0f / sum;
#pragma unroll
        for (int j = 0; j < E_; j++)
            sgw[(size_t)(b0 + row) * E_ + j] = lg[j] * inv;
    }
}

// ---------------------------------------------------------------------------
__global__ void __launch_bounds__(256)
combine_kernel(const h16* __restrict__ eo, const float* __restrict__ gw,
               const float* __restrict__ sgw, float* __restrict__ out)
{
    const int b = blockIdx.x * 2 + (threadIdx.x >> 7);
    const int o = threadIdx.x & 127;

    float v[E_];
#pragma unroll
    for (int e = 0; e < E_; e++)
        v[e] = __half2float(eo[((size_t)e * B + b) * OO + o]);

#pragma unroll
    for (int t = 0; t < T_; t++) {
        const float* g = gw + ((size_t)t * B + b) * NE;
        float s = 0.f;
#pragma unroll
        for (int j = 0; j < NS; j++) s += g[j] * v[j];
#pragma unroll
        for (int n = 0; n < NT_TASK; n++) s += g[NS + n] * v[NS + t * NT_TASK + n];
        out[((size_t)t * B + b) * OO + o] = s;
    }

    const float* sg = sgw + (size_t)b * E_;
    float s = 0.f;
#pragma unroll
    for (int e = 0; e < E_; e++) s += sg[e] * v[e];
    out[((size_t)3 * B + b) * OO + o] = s;
}

// ---------------------------------------------------------------------------
extern "C" void kernel_launch(void* const* d_in, const int* in_sizes, int n_in,
                              void* d_out, int out_size)
{
    const float* x     = (const float*)d_in[0];
    const float* ew1   = (const float*)d_in[1];
    const float* eb1   = (const float*)d_in[2];
    const float* eg1   = (const float*)d_in[3];
    const float* ebt1  = (const float*)d_in[4];
    const float* ew2   = (const float*)d_in[5];
    const float* eb2   = (const float*)d_in[6];
    const float* eg2   = (const float*)d_in[7];
    const float* ebt2  = (const float*)d_in[8];
    const float* ew3   = (const float*)d_in[9];
    const float* eb3   = (const float*)d_in[10];
    const float* eg3   = (const float*)d_in[11];
    const float* ebt3  = (const float*)d_in[12];
    const float* tg_w1 = (const float*)d_in[13];
    const float* tg_b1 = (const float*)d_in[14];
    const float* tg_w2 = (const float*)d_in[15];
    const float* tg_b2 = (const float*)d_in[16];
    const float* sg_w1 = (const float*)d_in[17];
    const float* sg_b1 = (const float*)d_in[18];
    const float* sg_w2 = (const float*)d_in[19];
    const float* sg_b2 = (const float*)d_in[20];
    float* out = (float*)d_out;

    static h16 *xh = nullptr, *w1t, *w2t, *w3t, *wgt, *eo;
    static float *gw, *sgw;
    if (!xh) {
        cudaGetSymbolAddress((void**)&xh,  g_xh);
        cudaGetSymbolAddress((void**)&w1t, g_w1t);
        cudaGetSymbolAddress((void**)&w2t, g_w2t);
        cudaGetSymbolAddress((void**)&w3t, g_w3t);
        cudaGetSymbolAddress((void**)&wgt, g_wgt);
        cudaGetSymbolAddress((void**)&eo,  g_eo);
        cudaGetSymbolAddress((void**)&gw,  g_gw);
        cudaGetSymbolAddress((void**)&sgw, g_sgw);
        cudaFuncSetAttribute(expert_fused, cudaFuncAttributeMaxDynamicSharedMemorySize,
                             (int)sizeof(SmemT));
        cudaFuncSetAttribute(gate_fused, cudaFuncAttributeMaxDynamicSharedMemorySize,
                             (int)sizeof(GSmem));
    }

    prep_x_gate<<<16384 + 512, 256>>>((const float4*)x, (unsigned*)xh, tg_w1, sg_w1, wgt);
    prep_weights<<<dim3(224, E_), 256>>>(ew1, ew2, ew3, w1t, w2t, w3t);

    gate_fused<<<B / 64, 256, sizeof(GSmem)>>>(
        xh, wgt, tg_b1, sg_b1, tg_w2, tg_b2, sg_w2, sg_b2, gw, sgw);

    expert_fused<<<dim3(E_, B / 128), TOW_THREADS, sizeof(SmemT)>>>(
        xh, w1t, w2t, w3t,
        eb1, eg1, ebt1, eb2, eg2, ebt2, eb3, eg3, ebt3, eo);

    combine_kernel<<<B / 2, 256>>>(eo, gw, sgw, out);
}

// round 13
// speedup vs baseline: 1.0960x; 1.0960x over previous
#include <cuda_runtime.h>
#include <cuda_fp16.h>
#include <math.h>
#include <stdint.h>

#define B  32768
#define D  512
#define H  256
#define OO 128
#define E_ 10
#define T_ 3
#define G_ 64
#define NS 4
#define NT_TASK 2
#define NE (NS + NT_TASK)

typedef __half h16;

// ---------------- scratch (allocation-free) ----------------
__device__ h16   g_xh[(size_t)B * D];
__device__ h16   g_w1t[(size_t)E_ * H * D];    // [E][N=256][K=512] fp16
__device__ h16   g_w2t[(size_t)E_ * H * H];    // [E][256][256]
__device__ h16   g_w3t[(size_t)E_ * OO * H];   // [E][128][256]
__device__ h16   g_wgt[(size_t)256 * D];       // combined gate W1^T [256][512]
__device__ h16   g_eo[(size_t)E_ * B * OO];    // expert outputs, fp16
__device__ float g_gw[(size_t)T_ * B * NE];
__device__ float g_sgw[(size_t)B * E_];

// ---------------- helpers ----------------
__device__ __forceinline__ void mma_fp16(float* c, const unsigned* a, const unsigned* b) {
    asm volatile(
        "mma.sync.aligned.m16n8k16.row.col.f32.f16.f16.f32 "
        "{%0,%1,%2,%3}, {%4,%5,%6,%7}, {%8,%9}, {%0,%1,%2,%3};\n"
        : "+f"(c[0]), "+f"(c[1]), "+f"(c[2]), "+f"(c[3])
        : "r"(a[0]), "r"(a[1]), "r"(a[2]), "r"(a[3]), "r"(b[0]), "r"(b[1]));
}
__device__ __forceinline__ unsigned pack_h2(h16 a, h16 b) {
    return (unsigned)__half_as_ushort(a) | ((unsigned)__half_as_ushort(b) << 16);
}
__device__ __forceinline__ void cp16(void* s, const void* g) {
    unsigned sa = (unsigned)__cvta_generic_to_shared(s);
    asm volatile("cp.async.cg.shared.global [%0], [%1], 16;\n" :: "r"(sa), "l"(g));
}
__device__ __forceinline__ void cp_commit() { asm volatile("cp.async.commit_group;\n"); }
template <int N2> __device__ __forceinline__ void cp_wait() {
    asm volatile("cp.async.wait_group %0;\n" :: "n"(N2));
}
__device__ __forceinline__ unsigned lds_u32(const void* p) {
    return (unsigned)__cvta_generic_to_shared(p);
}
__device__ __forceinline__ void ldsm_x4(unsigned* r, unsigned addr) {
    asm volatile("ldmatrix.sync.aligned.m8n8.x4.shared.b16 {%0,%1,%2,%3}, [%4];"
        : "=r"(r[0]), "=r"(r[1]), "=r"(r[2]), "=r"(r[3]) : "r"(addr));
}

// ---------------- prep kernels (merged) ----------------
__global__ void prep_x_gate(const float4* __restrict__ x4, unsigned* __restrict__ xh2,
                            const float* __restrict__ tg_w1, const float* __restrict__ sg_w1,
                            h16* __restrict__ wgt)
{
    const int bx = blockIdx.x, tid = threadIdx.x;
    if (bx < 16384) {
        int i = bx * 256 + tid;
        float4 v = x4[i];
        xh2[i * 2]     = pack_h2(__float2half_rn(v.x), __float2half_rn(v.y));
        xh2[i * 2 + 1] = pack_h2(__float2half_rn(v.z), __float2half_rn(v.w));
    } else {
        int i = (bx - 16384) * 256 + tid;
        int n = i >> 9, d = i & 511;
        float v;
        if (n < 192) {
            int t = n >> 6, g = n & 63;
            v = tg_w1[((size_t)t * D + d) * G_ + g];
        } else {
            v = sg_w1[(size_t)d * G_ + (n - 192)];
        }
        wgt[(size_t)n * D + d] = __float2half_rn(v);
    }
}

__global__ void prep_weights(const float* __restrict__ ew1, const float* __restrict__ ew2,
                             const float* __restrict__ ew3,
                             h16* __restrict__ w1t, h16* __restrict__ w2t, h16* __restrict__ w3t)
{
    __shared__ float t[32][33];
    const int e = blockIdx.y, bx = blockIdx.x, tid = threadIdx.x;
    const float* W; h16* T; int K, N, k0, n0;
    if (bx < 128)      { W = ew1; T = w1t; K = D; N = H;  k0 = (bx & 15) * 32;        n0 = (bx >> 4) * 32; }
    else if (bx < 192) { W = ew2; T = w2t; K = H; N = H;  k0 = ((bx - 128) & 7) * 32; n0 = ((bx - 128) >> 3) * 32; }
    else               { W = ew3; T = w3t; K = H; N = OO; k0 = ((bx - 192) & 7) * 32; n0 = ((bx - 192) >> 3) * 32; }
    const float* We = W + (size_t)e * K * N;
    for (int i = tid; i < 1024; i += 256) {
        int r = i >> 5, c = i & 31;
        t[r][c] = We[(size_t)(k0 + r) * N + n0 + c];
    }
    __syncthreads();
    size_t base = (size_t)e * N * K;
    for (int i = tid; i < 1024; i += 256) {
        int nn = i >> 5, kk = i & 31;
        T[base + (size_t)(n0 + nn) * K + k0 + kk] = __float2half_rn(t[kk][nn]);
    }
}

// ---------------------------------------------------------------------------
// Fused expert tower. CTA 64x256, 256 thr, 8 warps (2m x 4n), warp tile 32x64.
// 3-stage cp.async pipeline: ONE barrier per k32 step.
// ---------------------------------------------------------------------------
struct SmemT {
    h16   sB[3][256][40];  // 60 KB
    h16   sX[3][64][40];   // 15 KB
    h16   sH[64][264];     // 33 KB
    float red[4][64][2];   //  2 KB
};

__global__ void __launch_bounds__(256, 2)
expert_fused(const h16* __restrict__ xh,
             const h16* __restrict__ w1t, const h16* __restrict__ w2t, const h16* __restrict__ w3t,
             const float* __restrict__ eb1, const float* __restrict__ eg1, const float* __restrict__ ebt1,
             const float* __restrict__ eb2, const float* __restrict__ eg2, const float* __restrict__ ebt2,
             const float* __restrict__ eb3, const float* __restrict__ eg3, const float* __restrict__ ebt3,
             h16* __restrict__ eo)
{
    extern __shared__ char raw[];
    SmemT& sm = *reinterpret_cast<SmemT*>(raw);

    const int e   = blockIdx.x;
    const int b0  = blockIdx.y * 64;
    const int tid = threadIdx.x;
    const int wid = tid >> 5, lane = tid & 31;
    const int warp_m = wid & 1, warp_n = wid >> 1;   // 2 x 4
    const int gr = lane >> 2, tg = lane & 3;
    const int l8 = lane & 7, lm = lane >> 3;
    const int a_row0 = warp_m * 32 + (lm & 1) * 8 + l8;  // + mt*16
    const int a_kx   = (lm >> 1) * 8;
    const int b_row8 = (lm >> 1) * 8 + l8;               // + colbase + np*16
    const int b_kx   = (lm & 1) * 8;

    const h16* W1 = w1t + (size_t)e * H * D;
    const h16* W2 = w2t + (size_t)e * H * H;
    const h16* W3 = w3t + (size_t)e * OO * H;

    auto loadB = [&](const h16* T, int rows, int K, int buf, int k0) {
        for (int i = tid; i < rows * 4; i += 256) {
            int n = i >> 2, c = i & 3;
            cp16(&sm.sB[buf][n][c * 8], T + (size_t)n * K + k0 + c * 8);
        }
    };
    auto loadX = [&](int buf, int k0) {
        int r = tid >> 2, c = tid & 3;
        cp16(&sm.sX[buf][r][c * 8], xh + (size_t)(b0 + r) * D + k0 + c * 8);
    };

    float acc[2][8][4];
    float s[2][2], q[2][2], mean[2][2], rstd[2][2];

    // =================== Layer 1: 64x512 @ W1 -> 64x256 ===================
#pragma unroll
    for (int mt = 0; mt < 2; mt++)
#pragma unroll
        for (int nt = 0; nt < 8; nt++)
#pragma unroll
            for (int j = 0; j < 4; j++) acc[mt][nt][j] = 0.f;

    loadX(0, 0);  loadB(W1, 256, D, 0, 0);  cp_commit();
    loadX(1, 32); loadB(W1, 256, D, 1, 32); cp_commit();

    for (int ks = 0; ks < 16; ks++) {
        cp_wait<1>(); __syncthreads();
        const int sbuf = ks % 3;
#pragma unroll
        for (int ksub = 0; ksub < 2; ksub++) {
            const int koff = ksub * 16;
            unsigned a0[4], a1[4], bb[4][4];
            ldsm_x4(a0, lds_u32(&sm.sX[sbuf][a_row0][koff + a_kx]));
            ldsm_x4(a1, lds_u32(&sm.sX[sbuf][a_row0 + 16][koff + a_kx]));
#pragma unroll
            for (int np = 0; np < 4; np++)
                ldsm_x4(bb[np], lds_u32(&sm.sB[sbuf][warp_n * 64 + np * 16 + b_row8][koff + b_kx]));
#pragma unroll
            for (int np = 0; np < 4; np++) {
                mma_fp16(acc[0][2 * np],     a0, bb[np]);
                mma_fp16(acc[0][2 * np + 1], a0, bb[np] + 2);
                mma_fp16(acc[1][2 * np],     a1, bb[np]);
                mma_fp16(acc[1][2 * np + 1], a1, bb[np] + 2);
            }
        }
        if (ks + 2 < 16) {
            loadX((ks + 2) % 3, (ks + 2) * 32);
            loadB(W1, 256, D, (ks + 2) % 3, (ks + 2) * 32);
        }
        cp_commit();
    }
    __syncthreads();                           // all L1 reads done
    loadB(W2, 256, H, 0, 0);  cp_commit();     // prefetch L2 stages 0,1
    loadB(W2, 256, H, 1, 32); cp_commit();

    // ---- epilogue 1 -> sH ----
    {
        const float* be  = eb1  + (size_t)e * H;
        const float* ge  = eg1  + (size_t)e * H;
        const float* bte = ebt1 + (size_t)e * H;
        const int cbase = warp_n * 64 + tg * 2;
#pragma unroll
        for (int mt = 0; mt < 2; mt++) { s[mt][0] = s[mt][1] = q[mt][0] = q[mt][1] = 0.f; }
#pragma unroll
        for (int mt = 0; mt < 2; mt++)
#pragma unroll
            for (int nt = 0; nt < 8; nt++) {
                int c = cbase + nt * 8;
                float bv0 = be[c], bv1 = be[c + 1];
                acc[mt][nt][0] += bv0; acc[mt][nt][1] += bv1;
                acc[mt][nt][2] += bv0; acc[mt][nt][3] += bv1;
                s[mt][0] += acc[mt][nt][0] + acc[mt][nt][1];
                q[mt][0] = fmaf(acc[mt][nt][0], acc[mt][nt][0], fmaf(acc[mt][nt][1], acc[mt][nt][1], q[mt][0]));
                s[mt][1] += acc[mt][nt][2] + acc[mt][nt][3];
                q[mt][1] = fmaf(acc[mt][nt][2], acc[mt][nt][2], fmaf(acc[mt][nt][3], acc[mt][nt][3], q[mt][1]));
            }
#pragma unroll
        for (int mt = 0; mt < 2; mt++)
#pragma unroll
            for (int h = 0; h < 2; h++)
#pragma unroll
                for (int off = 1; off <= 2; off <<= 1) {
                    s[mt][h] += __shfl_xor_sync(0xffffffffu, s[mt][h], off);
                    q[mt][h] += __shfl_xor_sync(0xffffffffu, q[mt][h], off);
                }
        __syncthreads();
        if (tg == 0) {
#pragma unroll
            for (int mt = 0; mt < 2; mt++)
#pragma unroll
                for (int h = 0; h < 2; h++) {
                    int r = warp_m * 32 + mt * 16 + gr + h * 8;
                    sm.red[warp_n][r][0] = s[mt][h];
                    sm.red[warp_n][r][1] = q[mt][h];
                }
        }
        __syncthreads();
        const float invN = 1.0f / H;
#pragma unroll
        for (int mt = 0; mt < 2; mt++)
#pragma unroll
            for (int h = 0; h < 2; h++) {
                int r = warp_m * 32 + mt * 16 + gr + h * 8;
                float ss = sm.red[0][r][0] + sm.red[1][r][0] + sm.red[2][r][0] + sm.red[3][r][0];
                float qq = sm.red[0][r][1] + sm.red[1][r][1] + sm.red[2][r][1] + sm.red[3][r][1];
                float m = ss * invN;
                mean[mt][h] = m;
                rstd[mt][h] = rsqrtf(qq * invN - m * m + 1e-5f);
            }
#pragma unroll
        for (int mt = 0; mt < 2; mt++) {
            int r0 = warp_m * 32 + mt * 16 + gr;
#pragma unroll
            for (int nt = 0; nt < 8; nt++) {
                int c = cbase + nt * 8;
                float g0 = ge[c], g1 = ge[c + 1], t0 = bte[c], t1 = bte[c + 1];
                float v00 = fmaxf((acc[mt][nt][0] - mean[mt][0]) * rstd[mt][0] * g0 + t0, 0.f);
                float v01 = fmaxf((acc[mt][nt][1] - mean[mt][0]) * rstd[mt][0] * g1 + t1, 0.f);
                float v10 = fmaxf((acc[mt][nt][2] - mean[mt][1]) * rstd[mt][1] * g0 + t0, 0.f);
                float v11 = fmaxf((acc[mt][nt][3] - mean[mt][1]) * rstd[mt][1] * g1 + t1, 0.f);
                *(unsigned*)&sm.sH[r0][c]     = pack_h2(__float2half_rn(v00), __float2half_rn(v01));
                *(unsigned*)&sm.sH[r0 + 8][c] = pack_h2(__float2half_rn(v10), __float2half_rn(v11));
            }
        }
    }

    // =================== Layer 2: sH @ W2 -> 64x256 ===================
#pragma unroll
    for (int mt = 0; mt < 2; mt++)
#pragma unroll
        for (int nt = 0; nt < 8; nt++)
#pragma unroll
            for (int j = 0; j < 4; j++) acc[mt][nt][j] = 0.f;

    for (int ks = 0; ks < 8; ks++) {
        cp_wait<1>(); __syncthreads();
        const int sbuf = ks % 3;
#pragma unroll
        for (int ksub = 0; ksub < 2; ksub++) {
            const int koffA = ks * 32 + ksub * 16;
            const int koffB = ksub * 16;
            unsigned a0[4], a1[4], bb[4][4];
            ldsm_x4(a0, lds_u32(&sm.sH[a_row0][koffA + a_kx]));
            ldsm_x4(a1, lds_u32(&sm.sH[a_row0 + 16][koffA + a_kx]));
#pragma unroll
            for (int np = 0; np < 4; np++)
                ldsm_x4(bb[np], lds_u32(&sm.sB[sbuf][warp_n * 64 + np * 16 + b_row8][koffB + b_kx]));
#pragma unroll
            for (int np = 0; np < 4; np++) {
                mma_fp16(acc[0][2 * np],     a0, bb[np]);
                mma_fp16(acc[0][2 * np + 1], a0, bb[np] + 2);
                mma_fp16(acc[1][2 * np],     a1, bb[np]);
                mma_fp16(acc[1][2 * np + 1], a1, bb[np] + 2);
            }
        }
        if (ks + 2 < 8) loadB(W2, 256, H, (ks + 2) % 3, (ks + 2) * 32);
        cp_commit();
    }
    __syncthreads();
    loadB(W3, 128, H, 0, 0);  cp_commit();
    loadB(W3, 128, H, 1, 32); cp_commit();

    // ---- epilogue 2 -> sH ----
    {
        const float* be  = eb2  + (size_t)e * H;
        const float* ge  = eg2  + (size_t)e * H;
        const float* bte = ebt2 + (size_t)e * H;
        const int cbase = warp_n * 64 + tg * 2;
#pragma unroll
        for (int mt = 0; mt < 2; mt++) { s[mt][0] = s[mt][1] = q[mt][0] = q[mt][1] = 0.f; }
#pragma unroll
        for (int mt = 0; mt < 2; mt++)
#pragma unroll
            for (int nt = 0; nt < 8; nt++) {
                int c = cbase + nt * 8;
                float bv0 = be[c], bv1 = be[c + 1];
                acc[mt][nt][0] += bv0; acc[mt][nt][1] += bv1;
                acc[mt][nt][2] += bv0; acc[mt][nt][3] += bv1;
                s[mt][0] += acc[mt][nt][0] + acc[mt][nt][1];
                q[mt][0] = fmaf(acc[mt][nt][0], acc[mt][nt][0], fmaf(acc[mt][nt][1], acc[mt][nt][1], q[mt][0]));
                s[mt][1] += acc[mt][nt][2] + acc[mt][nt][3];
                q[mt][1] = fmaf(acc[mt][nt][2], acc[mt][nt][2], fmaf(acc[mt][nt][3], acc[mt][nt][3], q[mt][1]));
            }
#pragma unroll
        for (int mt = 0; mt < 2; mt++)
#pragma unroll
            for (int h = 0; h < 2; h++)
#pragma unroll
                for (int off = 1; off <= 2; off <<= 1) {
                    s[mt][h] += __shfl_xor_sync(0xffffffffu, s[mt][h], off);
                    q[mt][h] += __shfl_xor_sync(0xffffffffu, q[mt][h], off);
                }
        __syncthreads();
        if (tg == 0) {
#pragma unroll
            for (int mt = 0; mt < 2; mt++)
#pragma unroll
                for (int h = 0; h < 2; h++) {
                    int r = warp_m * 32 + mt * 16 + gr + h * 8;
                    sm.red[warp_n][r][0] = s[mt][h];
                    sm.red[warp_n][r][1] = q[mt][h];
                }
        }
        __syncthreads();
        const float invN = 1.0f / H;
#pragma unroll
        for (int mt = 0; mt < 2; mt++)
#pragma unroll
            for (int h = 0; h < 2; h++) {
                int r = warp_m * 32 + mt * 16 + gr + h * 8;
                float ss = sm.red[0][r][0] + sm.red[1][r][0] + sm.red[2][r][0] + sm.red[3][r][0];
                float qq = sm.red[0][r][1] + sm.red[1][r][1] + sm.red[2][r][1] + sm.red[3][r][1];
                float m = ss * invN;
                mean[mt][h] = m;
                rstd[mt][h] = rsqrtf(qq * invN - m * m + 1e-5f);
            }
        __syncthreads();   // all mainloop reads of sH done before overwrite
#pragma unroll
        for (int mt = 0; mt < 2; mt++) {
            int r0 = warp_m * 32 + mt * 16 + gr;
#pragma unroll
            for (int nt = 0; nt < 8; nt++) {
                int c = cbase + nt * 8;
                float g0 = ge[c], g1 = ge[c + 1], t0 = bte[c], t1 = bte[c + 1];
                float v00 = fmaxf((acc[mt][nt][0] - mean[mt][0]) * rstd[mt][0] * g0 + t0, 0.f);
                float v01 = fmaxf((acc[mt][nt][1] - mean[mt][0]) * rstd[mt][0] * g1 + t1, 0.f);
                float v10 = fmaxf((acc[mt][nt][2] - mean[mt][1]) * rstd[mt][1] * g0 + t0, 0.f);
                float v11 = fmaxf((acc[mt][nt][3] - mean[mt][1]) * rstd[mt][1] * g1 + t1, 0.f);
                *(unsigned*)&sm.sH[r0][c]     = pack_h2(__float2half_rn(v00), __float2half_rn(v01));
                *(unsigned*)&sm.sH[r0 + 8][c] = pack_h2(__float2half_rn(v10), __float2half_rn(v11));
            }
        }
    }
    __syncthreads();

    // =================== Layer 3: sH @ W3 -> 64x128 ===================
#pragma unroll
    for (int mt = 0; mt < 2; mt++)
#pragma unroll
        for (int nt = 0; nt < 4; nt++)
#pragma unroll
            for (int j = 0; j < 4; j++) acc[mt][nt][j] = 0.f;

    for (int ks = 0; ks < 8; ks++) {
        cp_wait<1>(); __syncthreads();
        const int sbuf = ks % 3;
#pragma unroll
        for (int ksub = 0; ksub < 2; ksub++) {
            const int koffA = ks * 32 + ksub * 16;
            const int koffB = ksub * 16;
            unsigned a0[4], a1[4], bb[2][4];
            ldsm_x4(a0, lds_u32(&sm.sH[a_row0][koffA + a_kx]));
            ldsm_x4(a1, lds_u32(&sm.sH[a_row0 + 16][koffA + a_kx]));
#pragma unroll
            for (int np = 0; np < 2; np++)
                ldsm_x4(bb[np], lds_u32(&sm.sB[sbuf][warp_n * 32 + np * 16 + b_row8][koffB + b_kx]));
#pragma unroll
            for (int np = 0; np < 2; np++) {
                mma_fp16(acc[0][2 * np],     a0, bb[np]);
                mma_fp16(acc[0][2 * np + 1], a0, bb[np] + 2);
                mma_fp16(acc[1][2 * np],     a1, bb[np]);
                mma_fp16(acc[1][2 * np + 1], a1, bb[np] + 2);
            }
        }
        if (ks + 2 < 8) loadB(W3, 128, H, (ks + 2) % 3, (ks + 2) * 32);
        cp_commit();
    }

    // ---- epilogue 3 -> eo (fp16) ----
    {
        const float* be  = eb3  + (size_t)e * OO;
        const float* ge  = eg3  + (size_t)e * OO;
        const float* bte = ebt3 + (size_t)e * OO;
        const int cbase = warp_n * 32 + tg * 2;
#pragma unroll
        for (int mt = 0; mt < 2; mt++) { s[mt][0] = s[mt][1] = q[mt][0] = q[mt][1] = 0.f; }
#pragma unroll
        for (int mt = 0; mt < 2; mt++)
#pragma unroll
            for (int nt = 0; nt < 4; nt++) {
                int c = cbase + nt * 8;
                float bv0 = be[c], bv1 = be[c + 1];
                acc[mt][nt][0] += bv0; acc[mt][nt][1] += bv1;
                acc[mt][nt][2] += bv0; acc[mt][nt][3] += bv1;
                s[mt][0] += acc[mt][nt][0] + acc[mt][nt][1];
                q[mt][0] = fmaf(acc[mt][nt][0], acc[mt][nt][0], fmaf(acc[mt][nt][1], acc[mt][nt][1], q[mt][0]));
                s[mt][1] += acc[mt][nt][2] + acc[mt][nt][3];
                q[mt][1] = fmaf(acc[mt][nt][2], acc[mt][nt][2], fmaf(acc[mt][nt][3], acc[mt][nt][3], q[mt][1]));
            }
#pragma unroll
        for (int mt = 0; mt < 2; mt++)
#pragma unroll
            for (int h = 0; h < 2; h++)
#pragma unroll
                for (int off = 1; off <= 2; off <<= 1) {
                    s[mt][h] += __shfl_xor_sync(0xffffffffu, s[mt][h], off);
                    q[mt][h] += __shfl_xor_sync(0xffffffffu, q[mt][h], off);
                }
        __syncthreads();
        if (tg == 0) {
#pragma unroll
            for (int mt = 0; mt < 2; mt++)
#pragma unroll
                for (int h = 0; h < 2; h++) {
                    int r = warp_m * 32 + mt * 16 + gr + h * 8;
                    sm.red[warp_n][r][0] = s[mt][h];
                    sm.red[warp_n][r][1] = q[mt][h];
                }
        }
        __syncthreads();
        const float invN = 1.0f / OO;
#pragma unroll
        for (int mt = 0; mt < 2; mt++)
#pragma unroll
            for (int h = 0; h < 2; h++) {
                int r = warp_m * 32 + mt * 16 + gr + h * 8;
                float ss = sm.red[0][r][0] + sm.red[1][r][0] + sm.red[2][r][0] + sm.red[3][r][0];
                float qq = sm.red[0][r][1] + sm.red[1][r][1] + sm.red[2][r][1] + sm.red[3][r][1];
                float m = ss * invN;
                mean[mt][h] = m;
                rstd[mt][h] = rsqrtf(qq * invN - m * m + 1e-5f);
            }
#pragma unroll
        for (int mt = 0; mt < 2; mt++) {
            int r0 = warp_m * 32 + mt * 16 + gr;
            size_t row0 = ((size_t)e * B + b0 + r0) * OO;
            size_t row1 = row0 + (size_t)8 * OO;
#pragma unroll
            for (int nt = 0; nt < 4; nt++) {
                int c = cbase + nt * 8;
                float g0 = ge[c], g1 = ge[c + 1], t0 = bte[c], t1 = bte[c + 1];
                float v00 = fmaxf((acc[mt][nt][0] - mean[mt][0]) * rstd[mt][0] * g0 + t0, 0.f);
                float v01 = fmaxf((acc[mt][nt][1] - mean[mt][0]) * rstd[mt][0] * g1 + t1, 0.f);
                float v10 = fmaxf((acc[mt][nt][2] - mean[mt][1]) * rstd[mt][1] * g0 + t0, 0.f);
                float v11 = fmaxf((acc[mt][nt][3] - mean[mt][1]) * rstd[mt][1] * g1 + t1, 0.f);
                *(unsigned*)&eo[row0 + c] = pack_h2(__float2half_rn(v00), __float2half_rn(v01));
                *(unsigned*)&eo[row1 + c] = pack_h2(__float2half_rn(v10), __float2half_rn(v11));
            }
        }
    }
}

// ---------------------------------------------------------------------------
// Fused gates (unchanged — passing, small share of runtime).
// ---------------------------------------------------------------------------
struct GSmem {
    h16   sB[2][256][40];
    h16   sX[2][64][40];
    h16   ghs[64][266];
    float w2s[T_ * G_ * NE];
    float sw2s[G_ * E_];
    float b1s[256];
    float b2s[T_ * NE + E_];
};

__global__ void __launch_bounds__(256, 2)
gate_fused(const h16* __restrict__ xh, const h16* __restrict__ wgt,
           const float* __restrict__ tg_b1, const float* __restrict__ sg_b1,
           const float* __restrict__ tg_w2, const float* __restrict__ tg_b2,
           const float* __restrict__ sg_w2, const float* __restrict__ sg_b2,
           float* __restrict__ gw, float* __restrict__ sgw)
{
    extern __shared__ char raw[];
    GSmem& sm = *reinterpret_cast<GSmem*>(raw);

    const int b0  = blockIdx.x * 64;
    const int tid = threadIdx.x;
    const int wid = tid >> 5, lane = tid & 31;
    const int warp_m = wid & 3, warp_n = wid >> 2;
    const int gr = lane >> 2, tg = lane & 3;
    const int ar = warp_m * 16 + gr;
    const int l8 = lane & 7, lm = lane >> 3;
    const int a_row = warp_m * 16 + (lm & 1) * 8 + l8;
    const int a_kx  = (lm >> 1) * 8;
    const int b_row8 = (lm >> 1) * 8 + l8;
    const int b_kx   = (lm & 1) * 8;

    for (int i = tid; i < T_ * G_ * NE; i += 256) sm.w2s[i] = tg_w2[i];
    for (int i = tid; i < G_ * E_; i += 256) sm.sw2s[i] = sg_w2[i];
    sm.b1s[tid] = (tid < 192) ? tg_b1[tid] : sg_b1[tid - 192];
    if (tid < T_ * NE) sm.b2s[tid] = tg_b2[tid];
    else if (tid < T_ * NE + E_) sm.b2s[tid] = sg_b2[tid - T_ * NE];

    auto loadB = [&](int buf, int k0) {
        for (int i = tid; i < 256 * 4; i += 256) {
            int n = i >> 2, c = i & 3;
            cp16(&sm.sB[buf][n][c * 8], wgt + (size_t)n * D + k0 + c * 8);
        }
    };
    auto loadX = [&](int buf, int k0) {
        int r = tid >> 2, c = tid & 3;
        cp16(&sm.sX[buf][r][c * 8], xh + (size_t)(b0 + r) * D + k0 + c * 8);
    };

    float acc[16][4];
#pragma unroll
    for (int nt = 0; nt < 16; nt++)
#pragma unroll
        for (int j = 0; j < 4; j++) acc[nt][j] = 0.f;

    int buf = 0;
    loadX(0, 0);
    loadB(0, 0);
    cp_commit();

    for (int ks = 0; ks < 16; ks++) {
        if (ks < 15) { loadX(buf ^ 1, (ks + 1) * 32); loadB(buf ^ 1, (ks + 1) * 32); }
        cp_commit();
        cp_wait<1>(); __syncthreads();
#pragma unroll
        for (int ksub = 0; ksub < 2; ksub++) {
            const int koff = ksub * 16;
            unsigned ah[4];
            ldsm_x4(ah, lds_u32(&sm.sX[buf][a_row][koff + a_kx]));
#pragma unroll
            for (int np = 0; np < 8; np++) {
                unsigned bb[4];
                ldsm_x4(bb, lds_u32(&sm.sB[buf][warp_n * 128 + np * 16 + b_row8][koff + b_kx]));
                mma_fp16(acc[2 * np],     ah, bb);
                mma_fp16(acc[2 * np + 1], ah, bb + 2);
            }
        }
        __syncthreads();
        buf ^= 1;
    }

    {
        const int cbase = warp_n * 128 + tg * 2;
#pragma unroll
        for (int nt = 0; nt < 16; nt++) {
            int c = cbase + nt * 8;
            float bv0 = sm.b1s[c], bv1 = sm.b1s[c + 1];
            float v00 = fmaxf(acc[nt][0] + bv0, 0.f);
            float v01 = fmaxf(acc[nt][1] + bv1, 0.f);
            float v10 = fmaxf(acc[nt][2] + bv0, 0.f);
            float v11 = fmaxf(acc[nt][3] + bv1, 0.f);
            *(unsigned*)&sm.ghs[ar][c]     = pack_h2(__float2half_rn(v00), __float2half_rn(v01));
            *(unsigned*)&sm.ghs[ar + 8][c] = pack_h2(__float2half_rn(v10), __float2half_rn(v11));
        }
    }
    __syncthreads();

    if (tid < 192) {
        const int row = tid & 63, t = tid >> 6;
        float lg[NE];
#pragma unroll
        for (int j = 0; j < NE; j++) lg[j] = sm.b2s[t * NE + j];
        for (int g = 0; g < G_; g++) {
            float gv = __half2float(sm.ghs[row][t * 64 + g]);
            const float* w = &sm.w2s[(t * G_ + g) * NE];
#pragma unroll
            for (int j = 0; j < NE; j++) lg[j] = fmaf(gv, w[j], lg[j]);
        }
        float mx = -1e30f;
#pragma unroll
        for (int j = 0; j < NE; j++) mx = fmaxf(mx, lg[j]);
        float sum = 0.f;
#pragma unroll
        for (int j = 0; j < NE; j++) { lg[j] = __expf(lg[j] - mx); sum += lg[j]; }
        float inv = 1.0f / sum;
#pragma unroll
        for (int j = 0; j < NE; j++)
            gw[((size_t)t * B + b0 + row) * NE + j] = lg[j] * inv;
    } else {
        const int row = tid - 192;
        float lg[E_];
#pragma unroll
        for (int j = 0; j < E_; j++) lg[j] = sm.b2s[T_ * NE + j];
        for (int g = 0; g < G_; g++) {
            float gv = __half2float(sm.ghs[row][192 + g]);
            const float* w = &sm.sw2s[g * E_];
#pragma unroll
            for (int j = 0; j < E_; j++) lg[j] = fmaf(gv, w[j], lg[j]);
        }
        float mx = -1e30f;
#pragma unroll
        for (int j = 0; j < E_; j++) mx = fmaxf(mx, lg[j]);
        float sum = 0.f;
#pragma unroll
        for (int j = 0; j < E_; j++) { lg[j] = __expf(lg[j] - mx); sum += lg[j]; }
        float inv = 1.0f / sum;
#pragma unroll
        for (int j = 0; j < E_; j++)
            sgw[(size_t)(b0 + row) * E_ + j] = lg[j] * inv;
    }
}

// ---------------------------------------------------------------------------
__global__ void __launch_bounds__(256)
combine_kernel(const h16* __restrict__ eo, const float* __restrict__ gw,
               const float* __restrict__ sgw, float* __restrict__ out)
{
    const int b = blockIdx.x * 2 + (threadIdx.x >> 7);
    const int o = threadIdx.x & 127;

    float v[E_];
#pragma unroll
    for (int e = 0; e < E_; e++)
        v[e] = __half2float(eo[((size_t)e * B + b) * OO + o]);

#pragma unroll
    for (int t = 0; t < T_; t++) {
        const float* g = gw + ((size_t)t * B + b) * NE;
        float s = 0.f;
#pragma unroll
        for (int j = 0; j < NS; j++) s += g[j] * v[j];
#pragma unroll
        for (int n = 0; n < NT_TASK; n++) s += g[NS + n] * v[NS + t * NT_TASK + n];
        out[((size_t)t * B + b) * OO + o] = s;
    }

    const float* sg = sgw + (size_t)b * E_;
    float s = 0.f;
#pragma unroll
    for (int e = 0; e < E_; e++) s += sg[e] * v[e];
    out[((size_t)3 * B + b) * OO + o] = s;
}

// ---------------------------------------------------------------------------
extern "C" void kernel_launch(void* const* d_in, const int* in_sizes, int n_in,
                              void* d_out, int out_size)
{
    const float* x     = (const float*)d_in[0];
    const float* ew1   = (const float*)d_in[1];
    const float* eb1   = (const float*)d_in[2];
    const float* eg1   = (const float*)d_in[3];
    const float* ebt1  = (const float*)d_in[4];
    const float* ew2   = (const float*)d_in[5];
    const float* eb2   = (const float*)d_in[6];
    const float* eg2   = (const float*)d_in[7];
    const float* ebt2  = (const float*)d_in[8];
    const float* ew3   = (const float*)d_in[9];
    const float* eb3   = (const float*)d_in[10];
    const float* eg3   = (const float*)d_in[11];
    const float* ebt3  = (const float*)d_in[12];
    const float* tg_w1 = (const float*)d_in[13];
    const float* tg_b1 = (const float*)d_in[14];
    const float* tg_w2 = (const float*)d_in[15];
    const float* tg_b2 = (const float*)d_in[16];
    const float* sg_w1 = (const float*)d_in[17];
    const float* sg_b1 = (const float*)d_in[18];
    const float* sg_w2 = (const float*)d_in[19];
    const float* sg_b2 = (const float*)d_in[20];
    float* out = (float*)d_out;

    static h16 *xh = nullptr, *w1t, *w2t, *w3t, *wgt, *eo;
    static float *gw, *sgw;
    if (!xh) {
        cudaGetSymbolAddress((void**)&xh,  g_xh);
        cudaGetSymbolAddress((void**)&w1t, g_w1t);
        cudaGetSymbolAddress((void**)&w2t, g_w2t);
        cudaGetSymbolAddress((void**)&w3t, g_w3t);
        cudaGetSymbolAddress((void**)&wgt, g_wgt);
        cudaGetSymbolAddress((void**)&eo,  g_eo);
        cudaGetSymbolAddress((void**)&gw,  g_gw);
        cudaGetSymbolAddress((void**)&sgw, g_sgw);
        cudaFuncSetAttribute(expert_fused, cudaFuncAttributeMaxDynamicSharedMemorySize,
                             (int)sizeof(SmemT));
        cudaFuncSetAttribute(gate_fused, cudaFuncAttributeMaxDynamicSharedMemorySize,
                             (int)sizeof(GSmem));
    }

    prep_x_gate<<<16384 + 512, 256>>>((const float4*)x, (unsigned*)xh, tg_w1, sg_w1, wgt);
    prep_weights<<<dim3(224, E_), 256>>>(ew1, ew2, ew3, w1t, w2t, w3t);

    gate_fused<<<B / 64, 256, sizeof(GSmem)>>>(
        xh, wgt, tg_b1, sg_b1, tg_w2, tg_b2, sg_w2, sg_b2, gw, sgw);

    expert_fused<<<dim3(E_, B / 64), 256, sizeof(SmemT)>>>(
        xh, w1t, w2t, w3t,
        eb1, eg1, ebt1, eb2, eg2, ebt2, eb3, eg3, ebt3, eo);

    combine_kernel<<<B / 2, 256>>>(eo, gw, sgw, out);
}

// round 14
// speedup vs baseline: 1.1214x; 1.0232x over previous
#include <cuda_runtime.h>
#include <cuda_fp16.h>
#include <math.h>
#include <stdint.h>

#define B  32768
#define D  512
#define H  256
#define OO 128
#define E_ 10
#define T_ 3
#define G_ 64
#define NS 4
#define NT_TASK 2
#define NE (NS + NT_TASK)

typedef __half h16;

// ---------------- scratch (allocation-free) ----------------
__device__ h16   g_xh[(size_t)B * D];
__device__ h16   g_w1t[(size_t)E_ * H * D];
__device__ h16   g_w2t[(size_t)E_ * H * H];
__device__ h16   g_w3t[(size_t)E_ * OO * H];
__device__ h16   g_wgt[(size_t)256 * D];
__device__ h16   g_eo[(size_t)E_ * B * OO];
__device__ float g_gw[(size_t)T_ * B * NE];
__device__ float g_sgw[(size_t)B * E_];

// ---------------- helpers ----------------
__device__ __forceinline__ void mma_fp16(float* c, const unsigned* a, const unsigned* b) {
    asm volatile(
        "mma.sync.aligned.m16n8k16.row.col.f32.f16.f16.f32 "
        "{%0,%1,%2,%3}, {%4,%5,%6,%7}, {%8,%9}, {%0,%1,%2,%3};\n"
        : "+f"(c[0]), "+f"(c[1]), "+f"(c[2]), "+f"(c[3])
        : "r"(a[0]), "r"(a[1]), "r"(a[2]), "r"(a[3]), "r"(b[0]), "r"(b[1]));
}
__device__ __forceinline__ unsigned pack_h2(h16 a, h16 b) {
    return (unsigned)__half_as_ushort(a) | ((unsigned)__half_as_ushort(b) << 16);
}
__device__ __forceinline__ void cp16(void* s, const void* g) {
    unsigned sa = (unsigned)__cvta_generic_to_shared(s);
    asm volatile("cp.async.cg.shared.global [%0], [%1], 16;\n" :: "r"(sa), "l"(g));
}
__device__ __forceinline__ void cp_commit() { asm volatile("cp.async.commit_group;\n"); }
template <int N2> __device__ __forceinline__ void cp_wait() {
    asm volatile("cp.async.wait_group %0;\n" :: "n"(N2));
}
__device__ __forceinline__ unsigned lds_u32(const void* p) {
    return (unsigned)__cvta_generic_to_shared(p);
}
__device__ __forceinline__ void ldsm_x4(unsigned* r, unsigned addr) {
    asm volatile("ldmatrix.sync.aligned.m8n8.x4.shared.b16 {%0,%1,%2,%3}, [%4];"
        : "=r"(r[0]), "=r"(r[1]), "=r"(r[2]), "=r"(r[3]) : "r"(addr));
}

// ---------------- prep kernels ----------------
__global__ void prep_x_gate(const float4* __restrict__ x4, unsigned* __restrict__ xh2,
                            const float* __restrict__ tg_w1, const float* __restrict__ sg_w1,
                            h16* __restrict__ wgt)
{
    const int bx = blockIdx.x, tid = threadIdx.x;
    if (bx < 16384) {
        int i = bx * 256 + tid;
        float4 v = x4[i];
        xh2[i * 2]     = pack_h2(__float2half_rn(v.x), __float2half_rn(v.y));
        xh2[i * 2 + 1] = pack_h2(__float2half_rn(v.z), __float2half_rn(v.w));
    } else {
        int i = (bx - 16384) * 256 + tid;
        int n = i >> 9, d = i & 511;
        float v;
        if (n < 192) {
            int t = n >> 6, g = n & 63;
            v = tg_w1[((size_t)t * D + d) * G_ + g];
        } else {
            v = sg_w1[(size_t)d * G_ + (n - 192)];
        }
        wgt[(size_t)n * D + d] = __float2half_rn(v);
    }
}

__global__ void prep_weights(const float* __restrict__ ew1, const float* __restrict__ ew2,
                             const float* __restrict__ ew3,
                             h16* __restrict__ w1t, h16* __restrict__ w2t, h16* __restrict__ w3t)
{
    __shared__ float t[32][33];
    const int e = blockIdx.y, bx = blockIdx.x, tid = threadIdx.x;
    const float* W; h16* T; int K, N, k0, n0;
    if (bx < 128)      { W = ew1; T = w1t; K = D; N = H;  k0 = (bx & 15) * 32;        n0 = (bx >> 4) * 32; }
    else if (bx < 192) { W = ew2; T = w2t; K = H; N = H;  k0 = ((bx - 128) & 7) * 32; n0 = ((bx - 128) >> 3) * 32; }
    else               { W = ew3; T = w3t; K = H; N = OO; k0 = ((bx - 192) & 7) * 32; n0 = ((bx - 192) >> 3) * 32; }
    const float* We = W + (size_t)e * K * N;
    for (int i = tid; i < 1024; i += 256) {
        int r = i >> 5, c = i & 31;
        t[r][c] = We[(size_t)(k0 + r) * N + n0 + c];
    }
    __syncthreads();
    size_t base = (size_t)e * N * K;
    for (int i = tid; i < 1024; i += 256) {
        int nn = i >> 5, kk = i & 31;
        T[base + (size_t)(n0 + nn) * K + k0 + kk] = __float2half_rn(t[kk][nn]);
    }
}

// ---------------------------------------------------------------------------
// Fused expert tower. CTA 64x256, 256 thr, 8 warps (2m x 4n), warp tile 32x64.
// 3-stage cp.async pipeline, rotating stage counters (no % ops).
// ---------------------------------------------------------------------------
struct SmemT {
    h16   sB[3][256][40];  // 60 KB
    h16   sX[3][64][40];   // 15 KB
    h16   sH[64][264];     // 33 KB
    float red[4][64][2];   //  2 KB
};

__global__ void __launch_bounds__(256, 2)
expert_fused(const h16* __restrict__ xh,
             const h16* __restrict__ w1t, const h16* __restrict__ w2t, const h16* __restrict__ w3t,
             const float* __restrict__ eb1, const float* __restrict__ eg1, const float* __restrict__ ebt1,
             const float* __restrict__ eb2, const float* __restrict__ eg2, const float* __restrict__ ebt2,
             const float* __restrict__ eb3, const float* __restrict__ eg3, const float* __restrict__ ebt3,
             h16* __restrict__ eo)
{
    extern __shared__ char raw[];
    SmemT& sm = *reinterpret_cast<SmemT*>(raw);

    const int e   = blockIdx.x;
    const int b0  = blockIdx.y * 64;
    const int tid = threadIdx.x;
    const int wid = tid >> 5, lane = tid & 31;
    const int warp_m = wid & 1, warp_n = wid >> 1;   // 2 x 4
    const int gr = lane >> 2, tg = lane & 3;
    const int l8 = lane & 7, lm = lane >> 3;
    const int a_row0 = warp_m * 32 + (lm & 1) * 8 + l8;
    const int a_kx   = (lm >> 1) * 8;
    const int b_row8 = (lm >> 1) * 8 + l8;
    const int b_kx   = (lm & 1) * 8;

    const h16* W1 = w1t + (size_t)e * H * D;
    const h16* W2 = w2t + (size_t)e * H * H;
    const h16* W3 = w3t + (size_t)e * OO * H;

    auto loadB = [&](const h16* T, int rows, int K, int buf, int k0) {
        for (int i = tid; i < rows * 4; i += 256) {
            int n = i >> 2, c = i & 3;
            cp16(&sm.sB[buf][n][c * 8], T + (size_t)n * K + k0 + c * 8);
        }
    };
    auto loadX = [&](int buf, int k0) {
        int r = tid >> 2, c = tid & 3;
        cp16(&sm.sX[buf][r][c * 8], xh + (size_t)(b0 + r) * D + k0 + c * 8);
    };

    float acc[2][8][4];
    float s[2][2], q[2][2], mean[2][2], rstd[2][2];

    // =================== Layer 1: 64x512 @ W1 -> 64x256 ===================
#pragma unroll
    for (int mt = 0; mt < 2; mt++)
#pragma unroll
        for (int nt = 0; nt < 8; nt++)
#pragma unroll
            for (int j = 0; j < 4; j++) acc[mt][nt][j] = 0.f;

    loadX(0, 0);  loadB(W1, 256, D, 0, 0);  cp_commit();
    loadX(1, 32); loadB(W1, 256, D, 1, 32); cp_commit();

    {
        int sbuf = 0, pf = 2;
        for (int ks = 0; ks < 16; ks++) {
            cp_wait<1>(); __syncthreads();
#pragma unroll
            for (int ksub = 0; ksub < 2; ksub++) {
                const int koff = ksub * 16;
                unsigned a0[4], a1[4], bb[4][4];
                ldsm_x4(a0, lds_u32(&sm.sX[sbuf][a_row0][koff + a_kx]));
                ldsm_x4(a1, lds_u32(&sm.sX[sbuf][a_row0 + 16][koff + a_kx]));
#pragma unroll
                for (int np = 0; np < 4; np++)
                    ldsm_x4(bb[np], lds_u32(&sm.sB[sbuf][warp_n * 64 + np * 16 + b_row8][koff + b_kx]));
#pragma unroll
                for (int np = 0; np < 4; np++) {
                    mma_fp16(acc[0][2 * np],     a0, bb[np]);
                    mma_fp16(acc[0][2 * np + 1], a0, bb[np] + 2);
                    mma_fp16(acc[1][2 * np],     a1, bb[np]);
                    mma_fp16(acc[1][2 * np + 1], a1, bb[np] + 2);
                }
            }
            if (ks + 2 < 16) {
                loadX(pf, (ks + 2) * 32);
                loadB(W1, 256, D, pf, (ks + 2) * 32);
            }
            cp_commit();
            sbuf = (sbuf == 2) ? 0 : sbuf + 1;
            pf   = (pf   == 2) ? 0 : pf + 1;
        }
    }
    __syncthreads();
    loadB(W2, 256, H, 0, 0);  cp_commit();
    loadB(W2, 256, H, 1, 32); cp_commit();

    // ---- epilogue 1 -> sH ----
    {
        const float* be  = eb1  + (size_t)e * H;
        const float* ge  = eg1  + (size_t)e * H;
        const float* bte = ebt1 + (size_t)e * H;
        const int cbase = warp_n * 64 + tg * 2;
#pragma unroll
        for (int mt = 0; mt < 2; mt++) { s[mt][0] = s[mt][1] = q[mt][0] = q[mt][1] = 0.f; }
#pragma unroll
        for (int mt = 0; mt < 2; mt++)
#pragma unroll
            for (int nt = 0; nt < 8; nt++) {
                int c = cbase + nt * 8;
                float bv0 = be[c], bv1 = be[c + 1];
                acc[mt][nt][0] += bv0; acc[mt][nt][1] += bv1;
                acc[mt][nt][2] += bv0; acc[mt][nt][3] += bv1;
                s[mt][0] += acc[mt][nt][0] + acc[mt][nt][1];
                q[mt][0] = fmaf(acc[mt][nt][0], acc[mt][nt][0], fmaf(acc[mt][nt][1], acc[mt][nt][1], q[mt][0]));
                s[mt][1] += acc[mt][nt][2] + acc[mt][nt][3];
                q[mt][1] = fmaf(acc[mt][nt][2], acc[mt][nt][2], fmaf(acc[mt][nt][3], acc[mt][nt][3], q[mt][1]));
            }
#pragma unroll
        for (int mt = 0; mt < 2; mt++)
#pragma unroll
            for (int h = 0; h < 2; h++)
#pragma unroll
                for (int off = 1; off <= 2; off <<= 1) {
                    s[mt][h] += __shfl_xor_sync(0xffffffffu, s[mt][h], off);
                    q[mt][h] += __shfl_xor_sync(0xffffffffu, q[mt][h], off);
                }
        __syncthreads();
        if (tg == 0) {
#pragma unroll
            for (int mt = 0; mt < 2; mt++)
#pragma unroll
                for (int h = 0; h < 2; h++) {
                    int r = warp_m * 32 + mt * 16 + gr + h * 8;
                    sm.red[warp_n][r][0] = s[mt][h];
                    sm.red[warp_n][r][1] = q[mt][h];
                }
        }
        __syncthreads();
        const float invN = 1.0f / H;
#pragma unroll
        for (int mt = 0; mt < 2; mt++)
#pragma unroll
            for (int h = 0; h < 2; h++) {
                int r = warp_m * 32 + mt * 16 + gr + h * 8;
                float ss = sm.red[0][r][0] + sm.red[1][r][0] + sm.red[2][r][0] + sm.red[3][r][0];
                float qq = sm.red[0][r][1] + sm.red[1][r][1] + sm.red[2][r][1] + sm.red[3][r][1];
                float m = ss * invN;
                mean[mt][h] = m;
                rstd[mt][h] = rsqrtf(qq * invN - m * m + 1e-5f);
            }
#pragma unroll
        for (int mt = 0; mt < 2; mt++) {
            int r0 = warp_m * 32 + mt * 16 + gr;
#pragma unroll
            for (int nt = 0; nt < 8; nt++) {
                int c = cbase + nt * 8;
                float g0 = ge[c], g1 = ge[c + 1], t0 = bte[c], t1 = bte[c + 1];
                float v00 = fmaxf((acc[mt][nt][0] - mean[mt][0]) * rstd[mt][0] * g0 + t0, 0.f);
                float v01 = fmaxf((acc[mt][nt][1] - mean[mt][0]) * rstd[mt][0] * g1 + t1, 0.f);
                float v10 = fmaxf((acc[mt][nt][2] - mean[mt][1]) * rstd[mt][1] * g0 + t0, 0.f);
                float v11 = fmaxf((acc[mt][nt][3] - mean[mt][1]) * rstd[mt][1] * g1 + t1, 0.f);
                *(unsigned*)&sm.sH[r0][c]     = pack_h2(__float2half_rn(v00), __float2half_rn(v01));
                *(unsigned*)&sm.sH[r0 + 8][c] = pack_h2(__float2half_rn(v10), __float2half_rn(v11));
            }
        }
    }

    // =================== Layer 2: sH @ W2 -> 64x256 ===================
#pragma unroll
    for (int mt = 0; mt < 2; mt++)
#pragma unroll
        for (int nt = 0; nt < 8; nt++)
#pragma unroll
            for (int j = 0; j < 4; j++) acc[mt][nt][j] = 0.f;

    {
        int sbuf = 0, pf = 2;
        for (int ks = 0; ks < 8; ks++) {
            cp_wait<1>(); __syncthreads();
#pragma unroll
            for (int ksub = 0; ksub < 2; ksub++) {
                const int koffA = ks * 32 + ksub * 16;
                const int koffB = ksub * 16;
                unsigned a0[4], a1[4], bb[4][4];
                ldsm_x4(a0, lds_u32(&sm.sH[a_row0][koffA + a_kx]));
                ldsm_x4(a1, lds_u32(&sm.sH[a_row0 + 16][koffA + a_kx]));
#pragma unroll
                for (int np = 0; np < 4; np++)
                    ldsm_x4(bb[np], lds_u32(&sm.sB[sbuf][warp_n * 64 + np * 16 + b_row8][koffB + b_kx]));
#pragma unroll
                for (int np = 0; np < 4; np++) {
                    mma_fp16(acc[0][2 * np],     a0, bb[np]);
                    mma_fp16(acc[0][2 * np + 1], a0, bb[np] + 2);
                    mma_fp16(acc[1][2 * np],     a1, bb[np]);
                    mma_fp16(acc[1][2 * np + 1], a1, bb[np] + 2);
                }
            }
            if (ks + 2 < 8) loadB(W2, 256, H, pf, (ks + 2) * 32);
            cp_commit();
            sbuf = (sbuf == 2) ? 0 : sbuf + 1;
            pf   = (pf   == 2) ? 0 : pf + 1;
        }
    }
    __syncthreads();
    loadB(W3, 128, H, 0, 0);  cp_commit();
    loadB(W3, 128, H, 1, 32); cp_commit();

    // ---- epilogue 2 -> sH ----
    {
        const float* be  = eb2  + (size_t)e * H;
        const float* ge  = eg2  + (size_t)e * H;
        const float* bte = ebt2 + (size_t)e * H;
        const int cbase = warp_n * 64 + tg * 2;
#pragma unroll
        for (int mt = 0; mt < 2; mt++) { s[mt][0] = s[mt][1] = q[mt][0] = q[mt][1] = 0.f; }
#pragma unroll
        for (int mt = 0; mt < 2; mt++)
#pragma unroll
            for (int nt = 0; nt < 8; nt++) {
                int c = cbase + nt * 8;
                float bv0 = be[c], bv1 = be[c + 1];
                acc[mt][nt][0] += bv0; acc[mt][nt][1] += bv1;
                acc[mt][nt][2] += bv0; acc[mt][nt][3] += bv1;
                s[mt][0] += acc[mt][nt][0] + acc[mt][nt][1];
                q[mt][0] = fmaf(acc[mt][nt][0], acc[mt][nt][0], fmaf(acc[mt][nt][1], acc[mt][nt][1], q[mt][0]));
                s[mt][1] += acc[mt][nt][2] + acc[mt][nt][3];
                q[mt][1] = fmaf(acc[mt][nt][2], acc[mt][nt][2], fmaf(acc[mt][nt][3], acc[mt][nt][3], q[mt][1]));
            }
#pragma unroll
        for (int mt = 0; mt < 2; mt++)
#pragma unroll
            for (int h = 0; h < 2; h++)
#pragma unroll
                for (int off = 1; off <= 2; off <<= 1) {
                    s[mt][h] += __shfl_xor_sync(0xffffffffu, s[mt][h], off);
                    q[mt][h] += __shfl_xor_sync(0xffffffffu, q[mt][h], off);
                }
        __syncthreads();
        if (tg == 0) {
#pragma unroll
            for (int mt = 0; mt < 2; mt++)
#pragma unroll
                for (int h = 0; h < 2; h++) {
                    int r = warp_m * 32 + mt * 16 + gr + h * 8;
                    sm.red[warp_n][r][0] = s[mt][h];
                    sm.red[warp_n][r][1] = q[mt][h];
                }
        }
        __syncthreads();
        const float invN = 1.0f / H;
#pragma unroll
        for (int mt = 0; mt < 2; mt++)
#pragma unroll
            for (int h = 0; h < 2; h++) {
                int r = warp_m * 32 + mt * 16 + gr + h * 8;
                float ss = sm.red[0][r][0] + sm.red[1][r][0] + sm.red[2][r][0] + sm.red[3][r][0];
                float qq = sm.red[0][r][1] + sm.red[1][r][1] + sm.red[2][r][1] + sm.red[3][r][1];
                float m = ss * invN;
                mean[mt][h] = m;
                rstd[mt][h] = rsqrtf(qq * invN - m * m + 1e-5f);
            }
        __syncthreads();
#pragma unroll
        for (int mt = 0; mt < 2; mt++) {
            int r0 = warp_m * 32 + mt * 16 + gr;
#pragma unroll
            for (int nt = 0; nt < 8; nt++) {
                int c = cbase + nt * 8;
                float g0 = ge[c], g1 = ge[c + 1], t0 = bte[c], t1 = bte[c + 1];
                float v00 = fmaxf((acc[mt][nt][0] - mean[mt][0]) * rstd[mt][0] * g0 + t0, 0.f);
                float v01 = fmaxf((acc[mt][nt][1] - mean[mt][0]) * rstd[mt][0] * g1 + t1, 0.f);
                float v10 = fmaxf((acc[mt][nt][2] - mean[mt][1]) * rstd[mt][1] * g0 + t0, 0.f);
                float v11 = fmaxf((acc[mt][nt][3] - mean[mt][1]) * rstd[mt][1] * g1 + t1, 0.f);
                *(unsigned*)&sm.sH[r0][c]     = pack_h2(__float2half_rn(v00), __float2half_rn(v01));
                *(unsigned*)&sm.sH[r0 + 8][c] = pack_h2(__float2half_rn(v10), __float2half_rn(v11));
            }
        }
    }
    __syncthreads();

    // =================== Layer 3: sH @ W3 -> 64x128 ===================
#pragma unroll
    for (int mt = 0; mt < 2; mt++)
#pragma unroll
        for (int nt = 0; nt < 4; nt++)
#pragma unroll
            for (int j = 0; j < 4; j++) acc[mt][nt][j] = 0.f;

    {
        int sbuf = 0, pf = 2;
        for (int ks = 0; ks < 8; ks++) {
            cp_wait<1>(); __syncthreads();
#pragma unroll
            for (int ksub = 0; ksub < 2; ksub++) {
                const int koffA = ks * 32 + ksub * 16;
                const int koffB = ksub * 16;
                unsigned a0[4], a1[4], bb[2][4];
                ldsm_x4(a0, lds_u32(&sm.sH[a_row0][koffA + a_kx]));
                ldsm_x4(a1, lds_u32(&sm.sH[a_row0 + 16][koffA + a_kx]));
#pragma unroll
                for (int np = 0; np < 2; np++)
                    ldsm_x4(bb[np], lds_u32(&sm.sB[sbuf][warp_n * 32 + np * 16 + b_row8][koffB + b_kx]));
#pragma unroll
                for (int np = 0; np < 2; np++) {
                    mma_fp16(acc[0][2 * np],     a0, bb[np]);
                    mma_fp16(acc[0][2 * np + 1], a0, bb[np] + 2);
                    mma_fp16(acc[1][2 * np],     a1, bb[np]);
                    mma_fp16(acc[1][2 * np + 1], a1, bb[np] + 2);
                }
            }
            if (ks + 2 < 8) loadB(W3, 128, H, pf, (ks + 2) * 32);
            cp_commit();
            sbuf = (sbuf == 2) ? 0 : sbuf + 1;
            pf   = (pf   == 2) ? 0 : pf + 1;
        }
    }

    // ---- epilogue 3 -> eo (fp16) ----
    {
        const float* be  = eb3  + (size_t)e * OO;
        const float* ge  = eg3  + (size_t)e * OO;
        const float* bte = ebt3 + (size_t)e * OO;
        const int cbase = warp_n * 32 + tg * 2;
#pragma unroll
        for (int mt = 0; mt < 2; mt++) { s[mt][0] = s[mt][1] = q[mt][0] = q[mt][1] = 0.f; }
#pragma unroll
        for (int mt = 0; mt < 2; mt++)
#pragma unroll
            for (int nt = 0; nt < 4; nt++) {
                int c = cbase + nt * 8;
                float bv0 = be[c], bv1 = be[c + 1];
                acc[mt][nt][0] += bv0; acc[mt][nt][1] += bv1;
                acc[mt][nt][2] += bv0; acc[mt][nt][3] += bv1;
                s[mt][0] += acc[mt][nt][0] + acc[mt][nt][1];
                q[mt][0] = fmaf(acc[mt][nt][0], acc[mt][nt][0], fmaf(acc[mt][nt][1], acc[mt][nt][1], q[mt][0]));
                s[mt][1] += acc[mt][nt][2] + acc[mt][nt][3];
                q[mt][1] = fmaf(acc[mt][nt][2], acc[mt][nt][2], fmaf(acc[mt][nt][3], acc[mt][nt][3], q[mt][1]));
            }
#pragma unroll
        for (int mt = 0; mt < 2; mt++)
#pragma unroll
            for (int h = 0; h < 2; h++)
#pragma unroll
                for (int off = 1; off <= 2; off <<= 1) {
                    s[mt][h] += __shfl_xor_sync(0xffffffffu, s[mt][h], off);
                    q[mt][h] += __shfl_xor_sync(0xffffffffu, q[mt][h], off);
                }
        __syncthreads();
        if (tg == 0) {
#pragma unroll
            for (int mt = 0; mt < 2; mt++)
#pragma unroll
                for (int h = 0; h < 2; h++) {
                    int r = warp_m * 32 + mt * 16 + gr + h * 8;
                    sm.red[warp_n][r][0] = s[mt][h];
                    sm.red[warp_n][r][1] = q[mt][h];
                }
        }
        __syncthreads();
        const float invN = 1.0f / OO;
#pragma unroll
        for (int mt = 0; mt < 2; mt++)
#pragma unroll
            for (int h = 0; h < 2; h++) {
                int r = warp_m * 32 + mt * 16 + gr + h * 8;
                float ss = sm.red[0][r][0] + sm.red[1][r][0] + sm.red[2][r][0] + sm.red[3][r][0];
                float qq = sm.red[0][r][1] + sm.red[1][r][1] + sm.red[2][r][1] + sm.red[3][r][1];
                float m = ss * invN;
                mean[mt][h] = m;
                rstd[mt][h] = rsqrtf(qq * invN - m * m + 1e-5f);
            }
#pragma unroll
        for (int mt = 0; mt < 2; mt++) {
            int r0 = warp_m * 32 + mt * 16 + gr;
            size_t row0 = ((size_t)e * B + b0 + r0) * OO;
            size_t row1 = row0 + (size_t)8 * OO;
#pragma unroll
            for (int nt = 0; nt < 4; nt++) {
                int c = cbase + nt * 8;
                float g0 = ge[c], g1 = ge[c + 1], t0 = bte[c], t1 = bte[c + 1];
                float v00 = fmaxf((acc[mt][nt][0] - mean[mt][0]) * rstd[mt][0] * g0 + t0, 0.f);
                float v01 = fmaxf((acc[mt][nt][1] - mean[mt][0]) * rstd[mt][0] * g1 + t1, 0.f);
                float v10 = fmaxf((acc[mt][nt][2] - mean[mt][1]) * rstd[mt][1] * g0 + t0, 0.f);
                float v11 = fmaxf((acc[mt][nt][3] - mean[mt][1]) * rstd[mt][1] * g1 + t1, 0.f);
                *(unsigned*)&eo[row0 + c] = pack_h2(__float2half_rn(v00), __float2half_rn(v01));
                *(unsigned*)&eo[row1 + c] = pack_h2(__float2half_rn(v10), __float2half_rn(v11));
            }
        }
    }
}

// ---------------------------------------------------------------------------
// Fused gates (unchanged).
// ---------------------------------------------------------------------------
struct GSmem {
    h16   sB[2][256][40];
    h16   sX[2][64][40];
    h16   ghs[64][266];
    float w2s[T_ * G_ * NE];
    float sw2s[G_ * E_];
    float b1s[256];
    float b2s[T_ * NE + E_];
};

__global__ void __launch_bounds__(256, 2)
gate_fused(const h16* __restrict__ xh, const h16* __restrict__ wgt,
           const float* __restrict__ tg_b1, const float* __restrict__ sg_b1,
           const float* __restrict__ tg_w2, const float* __restrict__ tg_b2,
           const float* __restrict__ sg_w2, const float* __restrict__ sg_b2,
           float* __restrict__ gw, float* __restrict__ sgw)
{
    extern __shared__ char raw[];
    GSmem& sm = *reinterpret_cast<GSmem*>(raw);

    const int b0  = blockIdx.x * 64;
    const int tid = threadIdx.x;
    const int wid = tid >> 5, lane = tid & 31;
    const int warp_m = wid & 3, warp_n = wid >> 2;
    const int gr = lane >> 2, tg = lane & 3;
    const int ar = warp_m * 16 + gr;
    const int l8 = lane & 7, lm = lane >> 3;
    const int a_row = warp_m * 16 + (lm & 1) * 8 + l8;
    const int a_kx  = (lm >> 1) * 8;
    const int b_row8 = (lm >> 1) * 8 + l8;
    const int b_kx   = (lm & 1) * 8;

    for (int i = tid; i < T_ * G_ * NE; i += 256) sm.w2s[i] = tg_w2[i];
    for (int i = tid; i < G_ * E_; i += 256) sm.sw2s[i] = sg_w2[i];
    sm.b1s[tid] = (tid < 192) ? tg_b1[tid] : sg_b1[tid - 192];
    if (tid < T_ * NE) sm.b2s[tid] = tg_b2[tid];
    else if (tid < T_ * NE + E_) sm.b2s[tid] = sg_b2[tid - T_ * NE];

    auto loadB = [&](int buf, int k0) {
        for (int i = tid; i < 256 * 4; i += 256) {
            int n = i >> 2, c = i & 3;
            cp16(&sm.sB[buf][n][c * 8], wgt + (size_t)n * D + k0 + c * 8);
        }
    };
    auto loadX = [&](int buf, int k0) {
        int r = tid >> 2, c = tid & 3;
        cp16(&sm.sX[buf][r][c * 8], xh + (size_t)(b0 + r) * D + k0 + c * 8);
    };

    float acc[16][4];
#pragma unroll
    for (int nt = 0; nt < 16; nt++)
#pragma unroll
        for (int j = 0; j < 4; j++) acc[nt][j] = 0.f;

    int buf = 0;
    loadX(0, 0);
    loadB(0, 0);
    cp_commit();

    for (int ks = 0; ks < 16; ks++) {
        if (ks < 15) { loadX(buf ^ 1, (ks + 1) * 32); loadB(buf ^ 1, (ks + 1) * 32); }
        cp_commit();
        cp_wait<1>(); __syncthreads();
#pragma unroll
        for (int ksub = 0; ksub < 2; ksub++) {
            const int koff = ksub * 16;
            unsigned ah[4];
            ldsm_x4(ah, lds_u32(&sm.sX[buf][a_row][koff + a_kx]));
#pragma unroll
            for (int np = 0; np < 8; np++) {
                unsigned bb[4];
                ldsm_x4(bb, lds_u32(&sm.sB[buf][warp_n * 128 + np * 16 + b_row8][koff + b_kx]));
                mma_fp16(acc[2 * np],     ah, bb);
                mma_fp16(acc[2 * np + 1], ah, bb + 2);
            }
        }
        __syncthreads();
        buf ^= 1;
    }

    {
        const int cbase = warp_n * 128 + tg * 2;
#pragma unroll
        for (int nt = 0; nt < 16; nt++) {
            int c = cbase + nt * 8;
            float bv0 = sm.b1s[c], bv1 = sm.b1s[c + 1];
            float v00 = fmaxf(acc[nt][0] + bv0, 0.f);
            float v01 = fmaxf(acc[nt][1] + bv1, 0.f);
            float v10 = fmaxf(acc[nt][2] + bv0, 0.f);
            float v11 = fmaxf(acc[nt][3] + bv1, 0.f);
            *(unsigned*)&sm.ghs[ar][c]     = pack_h2(__float2half_rn(v00), __float2half_rn(v01));
            *(unsigned*)&sm.ghs[ar + 8][c] = pack_h2(__float2half_rn(v10), __float2half_rn(v11));
        }
    }
    __syncthreads();

    if (tid < 192) {
        const int row = tid & 63, t = tid >> 6;
        float lg[NE];
#pragma unroll
        for (int j = 0; j < NE; j++) lg[j] = sm.b2s[t * NE + j];
        for (int g = 0; g < G_; g++) {
            float gv = __half2float(sm.ghs[row][t * 64 + g]);
            const float* w = &sm.w2s[(t * G_ + g) * NE];
#pragma unroll
            for (int j = 0; j < NE; j++) lg[j] = fmaf(gv, w[j], lg[j]);
        }
        float mx = -1e30f;
#pragma unroll
        for (int j = 0; j < NE; j++) mx = fmaxf(mx, lg[j]);
        float sum = 0.f;
#pragma unroll
        for (int j = 0; j < NE; j++) { lg[j] = __expf(lg[j] - mx); sum += lg[j]; }
        float inv = 1.0f / sum;
#pragma unroll
        for (int j = 0; j < NE; j++)
            gw[((size_t)t * B + b0 + row) * NE + j] = lg[j] * inv;
    } else {
        const int row = tid - 192;
        float lg[E_];
#pragma unroll
        for (int j = 0; j < E_; j++) lg[j] = sm.b2s[T_ * NE + j];
        for (int g = 0; g < G_; g++) {
            float gv = __half2float(sm.ghs[row][192 + g]);
            const float* w = &sm.sw2s[g * E_];
#pragma unroll
            for (int j = 0; j < E_; j++) lg[j] = fmaf(gv, w[j], lg[j]);
        }
        float mx = -1e30f;
#pragma unroll
        for (int j = 0; j < E_; j++) mx = fmaxf(mx, lg[j]);
        float sum = 0.f;
#pragma unroll
        for (int j = 0; j < E_; j++) { lg[j] = __expf(lg[j] - mx); sum += lg[j]; }
        float inv = 1.0f / sum;
#pragma unroll
        for (int j = 0; j < E_; j++)
            sgw[(size_t)(b0 + row) * E_ + j] = lg[j] * inv;
    }
}

// ---------------------------------------------------------------------------
__global__ void __launch_bounds__(256)
combine_kernel(const h16* __restrict__ eo, const float* __restrict__ gw,
               const float* __restrict__ sgw, float* __restrict__ out)
{
    const int b = blockIdx.x * 2 + (threadIdx.x >> 7);
    const int o = threadIdx.x & 127;

    float v[E_];
#pragma unroll
    for (int e = 0; e < E_; e++)
        v[e] = __half2float(eo[((size_t)e * B + b) * OO + o]);

#pragma unroll
    for (int t = 0; t < T_; t++) {
        const float* g = gw + ((size_t)t * B + b) * NE;
        float s = 0.f;
#pragma unroll
        for (int j = 0; j < NS; j++) s += g[j] * v[j];
#pragma unroll
        for (int n = 0; n < NT_TASK; n++) s += g[NS + n] * v[NS + t * NT_TASK + n];
        out[((size_t)t * B + b) * OO + o] = s;
    }

    const float* sg = sgw + (size_t)b * E_;
    float s = 0.f;
#pragma unroll
    for (int e = 0; e < E_; e++) s += sg[e] * v[e];
    out[((size_t)3 * B + b) * OO + o] = s;
}

// ---------------------------------------------------------------------------
extern "C" void kernel_launch(void* const* d_in, const int* in_sizes, int n_in,
                              void* d_out, int out_size)
{
    const float* x     = (const float*)d_in[0];
    const float* ew1   = (const float*)d_in[1];
    const float* eb1   = (const float*)d_in[2];
    const float* eg1   = (const float*)d_in[3];
    const float* ebt1  = (const float*)d_in[4];
    const float* ew2   = (const float*)d_in[5];
    const float* eb2   = (const float*)d_in[6];
    const float* eg2   = (const float*)d_in[7];
    const float* ebt2  = (const float*)d_in[8];
    const float* ew3   = (const float*)d_in[9];
    const float* eb3   = (const float*)d_in[10];
    const float* eg3   = (const float*)d_in[11];
    const float* ebt3  = (const float*)d_in[12];
    const float* tg_w1 = (const float*)d_in[13];
    const float* tg_b1 = (const float*)d_in[14];
    const float* tg_w2 = (const float*)d_in[15];
    const float* tg_b2 = (const float*)d_in[16];
    const float* sg_w1 = (const float*)d_in[17];
    const float* sg_b1 = (const float*)d_in[18];
    const float* sg_w2 = (const float*)d_in[19];
    const float* sg_b2 = (const float*)d_in[20];
    float* out = (float*)d_out;

    static h16 *xh = nullptr, *w1t, *w2t, *w3t, *wgt, *eo;
    static float *gw, *sgw;
    static cudaStream_t s1, s2;
    static cudaEvent_t evX, evW, evG;
    if (!xh) {
        cudaGetSymbolAddress((void**)&xh,  g_xh);
        cudaGetSymbolAddress((void**)&w1t, g_w1t);
        cudaGetSymbolAddress((void**)&w2t, g_w2t);
        cudaGetSymbolAddress((void**)&w3t, g_w3t);
        cudaGetSymbolAddress((void**)&wgt, g_wgt);
        cudaGetSymbolAddress((void**)&eo,  g_eo);
        cudaGetSymbolAddress((void**)&gw,  g_gw);
        cudaGetSymbolAddress((void**)&sgw, g_sgw);
        cudaFuncSetAttribute(expert_fused, cudaFuncAttributeMaxDynamicSharedMemorySize,
                             (int)sizeof(SmemT));
        cudaFuncSetAttribute(gate_fused, cudaFuncAttributeMaxDynamicSharedMemorySize,
                             (int)sizeof(GSmem));
        cudaStreamCreateWithFlags(&s1, cudaStreamNonBlocking);
        cudaStreamCreateWithFlags(&s2, cudaStreamNonBlocking);
        cudaEventCreateWithFlags(&evX, cudaEventDisableTiming);
        cudaEventCreateWithFlags(&evW, cudaEventDisableTiming);
        cudaEventCreateWithFlags(&evG, cudaEventDisableTiming);
    }

    // prep: x+gate-weight on default stream; expert-weight transpose forked to s2
    prep_x_gate<<<16384 + 512, 256>>>((const float4*)x, (unsigned*)xh, tg_w1, sg_w1, wgt);
    cudaEventRecord(evX, 0);
    cudaStreamWaitEvent(s2, evX, 0);
    prep_weights<<<dim3(224, E_), 256, 0, s2>>>(ew1, ew2, ew3, w1t, w2t, w3t);
    cudaEventRecord(evW, s2);

    // gates forked to s1 (needs only prep_x_gate) — overlaps with expert tower
    cudaStreamWaitEvent(s1, evX, 0);
    gate_fused<<<B / 64, 256, sizeof(GSmem), s1>>>(
        xh, wgt, tg_b1, sg_b1, tg_w2, tg_b2, sg_w2, sg_b2, gw, sgw);
    cudaEventRecord(evG, s1);

    // expert tower on default stream (needs prep_weights too)
    cudaStreamWaitEvent(0, evW, 0);
    expert_fused<<<dim3(E_, B / 64), 256, sizeof(SmemT)>>>(
        xh, w1t, w2t, w3t,
        eb1, eg1, ebt1, eb2, eg2, ebt2, eb3, eg3, ebt3, eo);

    // combine joins gate stream
    cudaStreamWaitEvent(0, evG, 0);
    combine_kernel<<<B / 2, 256>>>(eo, gw, sgw, out);
}